// round 2
// baseline (speedup 1.0000x reference)
#include <cuda_runtime.h>
#include <math.h>

#define NB 256
#define NPER 128

// Global scratch (static device memory; no runtime allocation)
__device__ __align__(16) float g_P[(size_t)4 * NB * NPER * NPER]; // [sign][head][b][c][r]
__device__ float g_feats[4 * NB * 21];  // per chain: traces k2..8, nl k2..8, ll k2..8
__device__ float g_omega[NB * 2];

// ============================================================================
// Kernel 1: per-batch GCN + attention + dense P construction
// smem floats: An 0(16512) X 16512(4096) XW 20608(4096) Q2 24704(8320)
//              K2 33024(8320) Wb 41344(2048) dinv 43392(128) wcs 43520(4) zloc 43524(128)
// ============================================================================
#define SMB_FLOATS 43652

__global__ __launch_bounds__(256) void batch_kernel(
    const float* __restrict__ z_table, const float* __restrict__ conv_W, const float* __restrict__ conv_b,
    const float* __restrict__ k1_W, const float* __restrict__ k1_b,
    const float* __restrict__ q1_W, const float* __restrict__ q1_b,
    const float* __restrict__ k2_W, const float* __restrict__ k2_b,
    const float* __restrict__ q2_W, const float* __restrict__ q2_b,
    const int* __restrict__ z, const int* __restrict__ edge_row, const int* __restrict__ edge_col,
    const int* __restrict__ node_i, const int* __restrict__ node_j)
{
    extern __shared__ float sm[];
    float* An   = sm;             // stride 129
    float* X    = sm + 16512;     // 128x32
    float* XW   = sm + 20608;     // 128x32
    float* Q2   = sm + 24704;     // 128x65 padded
    float* K2   = sm + 33024;     // 128x65 padded
    float* Wb   = sm + 41344;     // up to 32x64
    float* dinv = sm + 43392;
    float* wcs  = sm + 43520;
    int*   zloc = (int*)(sm + 43524);

    const int tid   = threadIdx.x;
    const int b     = blockIdx.x;
    const int gbase = b * NPER;
    const int ebase = b * NPER * 8;
    const int li    = node_i[b] - gbase;
    const int lj    = node_j[b] - gbase;

    if (tid < NPER) {
        float dg = 9.f + (tid == li ? 1.f : 0.f) + (tid == lj ? 1.f : 0.f);
        dinv[tid] = rsqrtf(dg);
        zloc[tid] = z[gbase + tid];
    }
    for (int i = tid; i < 16512; i += 256) An[i] = 0.f;
    __syncthreads();

    // embedding gather
    for (int i = tid; i < 4096; i += 256) {
        int r = i >> 5, f = i & 31;
        X[i] = z_table[zloc[r] * 32 + f];
    }
    // dense normalized adjacency (all contributions to one cell are identical
    // values -> atomic order is bitwise-deterministic)
    for (int e = tid; e < 1024; e += 256) {
        int r = edge_row[ebase + e] - gbase;
        int c = edge_col[ebase + e] - gbase;
        atomicAdd(&An[c * 129 + r], dinv[r] * dinv[c]);
    }
    if (tid == 0) {
        atomicAdd(&An[lj * 129 + li], dinv[li] * dinv[lj]);  // cand i->j (col j)
        atomicAdd(&An[li * 129 + lj], dinv[li] * dinv[lj]);  // cand j->i (col i)
    }
    if (tid < NPER) atomicAdd(&An[tid * 129 + tid], dinv[tid] * dinv[tid]);  // self loop
    __syncthreads();

    // GCN layers: X <- (maybe relu)(An @ (X @ W_l) + b_l)
    for (int l = 0; l < 3; l++) {
        for (int i = tid; i < 1024; i += 256) Wb[i] = conv_W[l * 1024 + i];
        __syncthreads();
        for (int i = tid; i < 4096; i += 256) {
            int r = i >> 5, f = i & 31;
            float s = 0.f;
            #pragma unroll 8
            for (int m = 0; m < 32; m++) s = fmaf(X[r * 32 + m], Wb[m * 32 + f], s);
            XW[i] = s;
        }
        __syncthreads();
        for (int g = 0; g < 4; g++) {
            int grp = tid + g * 256;
            int c = grp >> 3, fg = (grp & 7) * 4;
            float4 acc = make_float4(conv_b[l * 32 + fg], conv_b[l * 32 + fg + 1],
                                     conv_b[l * 32 + fg + 2], conv_b[l * 32 + fg + 3]);
            for (int r = 0; r < 128; r++) {
                float av = An[c * 129 + r];
                float4 xw = *(const float4*)(XW + r * 32 + fg);
                acc.x = fmaf(av, xw.x, acc.x);
                acc.y = fmaf(av, xw.y, acc.y);
                acc.z = fmaf(av, xw.z, acc.z);
                acc.w = fmaf(av, xw.w, acc.w);
            }
            if (l < 2) {
                acc.x = fmaxf(acc.x, 0.f); acc.y = fmaxf(acc.y, 0.f);
                acc.z = fmaxf(acc.z, 0.f); acc.w = fmaxf(acc.w, 0.f);
            }
            *(float4*)(X + c * 32 + fg) = acc;
        }
        __syncthreads();
    }

    // Q path: leaky(X@k1_W+k1_b) @ k2_W + k2_b  -> Q2 (used at edge ROWS)
    for (int i = tid; i < 1024; i += 256) Wb[i] = k1_W[i];
    __syncthreads();
    for (int i = tid; i < 4096; i += 256) {
        int r = i >> 5, f = i & 31;
        float s = k1_b[f];
        #pragma unroll 8
        for (int m = 0; m < 32; m++) s = fmaf(X[r * 32 + m], Wb[m * 32 + f], s);
        XW[i] = (s > 0.f) ? s : 0.2f * s;
    }
    __syncthreads();
    for (int i = tid; i < 2048; i += 256) Wb[i] = k2_W[i];
    __syncthreads();
    for (int i = tid; i < 8192; i += 256) {
        int r = i >> 6, f = i & 63;
        float s = k2_b[f];
        #pragma unroll 8
        for (int m = 0; m < 32; m++) s = fmaf(XW[r * 32 + m], Wb[m * 64 + f], s);
        Q2[r * 65 + f] = s;
    }
    __syncthreads();
    // K path: leaky(X@q1_W+q1_b) @ q2_W + q2_b  -> K2 (used at edge COLS)
    for (int i = tid; i < 1024; i += 256) Wb[i] = q1_W[i];
    __syncthreads();
    for (int i = tid; i < 4096; i += 256) {
        int r = i >> 5, f = i & 31;
        float s = q1_b[f];
        #pragma unroll 8
        for (int m = 0; m < 32; m++) s = fmaf(X[r * 32 + m], Wb[m * 32 + f], s);
        XW[i] = (s > 0.f) ? s : 0.2f * s;
    }
    __syncthreads();
    for (int i = tid; i < 2048; i += 256) Wb[i] = q2_W[i];
    __syncthreads();
    for (int i = tid; i < 8192; i += 256) {
        int r = i >> 6, f = i & 63;
        float s = q2_b[f];
        #pragma unroll 8
        for (int m = 0; m < 32; m++) s = fmaf(XW[r * 32 + m], Wb[m * 64 + f], s);
        K2[r * 65 + f] = s;
    }
    __syncthreads();

    // Per-(col,head) logits + segment softmax -> dense P rows
    const int c = tid & 127;
    const int h = tid >> 7;
    const float isq = 0.17677669529663687f;  // 1/sqrt(32)

    float kv[32];
    #pragma unroll
    for (int f = 0; f < 32; f++) kv[f] = K2[c * 65 + h * 32 + f];

    float w[9];
    int rws[9];
    #pragma unroll
    for (int k = 0; k < 8; k++) {
        int r = edge_row[ebase + k * 128 + c] - gbase;
        rws[k] = r;
        float s = 0.f;
        #pragma unroll 8
        for (int f = 0; f < 32; f++) s = fmaf(Q2[r * 65 + h * 32 + f], kv[f], s);
        w[k] = s * isq;
    }
    int ne = 8;
    if (c == lj)      { rws[8] = li; ne = 9; }
    else if (c == li) { rws[8] = lj; ne = 9; }
    if (ne == 9) {
        int r = rws[8];
        float s = 0.f;
        #pragma unroll 8
        for (int f = 0; f < 32; f++) s = fmaf(Q2[r * 65 + h * 32 + f], kv[f], s);
        w[8] = s * isq;
        wcs[h * 2 + (c == li ? 1 : 0)] = 1.f / (1.f + expf(-w[8]));
    }
    float wmax = w[0];
    for (int k = 1; k < ne; k++) wmax = fmaxf(wmax, w[k]);
    float ews[8];
    float sump = 0.f, summ = 0.f;
    #pragma unroll
    for (int k = 0; k < 8; k++) {
        float e = expf(w[k] - wmax);
        ews[k] = e; sump += e; summ += e;
    }
    float ec = 0.f;
    if (ne == 9) { ec = expf(w[8] - wmax); sump += ec; }
    float invp = 1.f / (sump + 1e-16f);
    float invm = 1.f / (summ + 1e-16f);

    float rowp[128], rowm[128];
    for (int r = 0; r < 128; r++) { rowp[r] = 0.f; rowm[r] = 0.f; }
    #pragma unroll
    for (int k = 0; k < 8; k++) {
        rowp[rws[k]] += ews[k] * invp;
        rowm[rws[k]] += ews[k] * invm;
    }
    if (ne == 9) rowp[rws[8]] += ec * invp;

    size_t bp = ((size_t)h * 256 + b) * 16384 + (size_t)c * 128;
    size_t bm = ((size_t)(2 + h) * 256 + b) * 16384 + (size_t)c * 128;
    for (int r4 = 0; r4 < 128; r4 += 4) {
        *(float4*)&g_P[bp + r4] = make_float4(rowp[r4], rowp[r4+1], rowp[r4+2], rowp[r4+3]);
        *(float4*)&g_P[bm + r4] = make_float4(rowm[r4], rowm[r4+1], rowm[r4+2], rowm[r4+3]);
    }
    __syncthreads();
    if (tid < 2) g_omega[b * 2 + tid] = wcs[tid * 2] + wcs[tid * 2 + 1];
}

// ============================================================================
// Kernel 2: per-chain matrix power features (3 smem matmuls + extraction)
// ============================================================================
#define MSTRIDE 130   // == 2 mod 4: A column loads bank-split, B rows float2-ok
#define SMC_FLOATS (3 * 128 * MSTRIDE + 48)

__device__ __forceinline__ void block_sum(float v, float* red, float* slot, int tid) {
    #pragma unroll
    for (int off = 16; off; off >>= 1) v += __shfl_down_sync(0xffffffffu, v, off);
    if ((tid & 31) == 0) red[tid >> 5] = v;
    __syncthreads();
    if (tid == 0) {
        float s = red[0];
        #pragma unroll
        for (int ww = 1; ww < 8; ww++) s += red[ww];
        *slot = s;
    }
    __syncthreads();
}

__device__ __forceinline__ void mm128(const float* __restrict__ A, const float* __restrict__ B,
                                      float* __restrict__ C, int tid) {
    const int tr = (tid >> 4) * 8;
    const int tc = (tid & 15) * 8;
    float acc[8][8];
    #pragma unroll
    for (int i = 0; i < 8; i++)
        #pragma unroll
        for (int j = 0; j < 8; j++) acc[i][j] = 0.f;

    #pragma unroll 4
    for (int k = 0; k < 128; k++) {
        float a[8], bb[8];
        #pragma unroll
        for (int i = 0; i < 8; i++) a[i] = A[(tr + i) * MSTRIDE + k];
        const float2* Brow = (const float2*)(B + k * MSTRIDE + tc);
        #pragma unroll
        for (int u = 0; u < 4; u++) { float2 t = Brow[u]; bb[2*u] = t.x; bb[2*u+1] = t.y; }
        #pragma unroll
        for (int i = 0; i < 8; i++)
            #pragma unroll
            for (int j = 0; j < 8; j++) acc[i][j] = fmaf(a[i], bb[j], acc[i][j]);
    }
    #pragma unroll
    for (int i = 0; i < 8; i++)
        #pragma unroll
        for (int j = 0; j < 8; j++) C[(tr + i) * MSTRIDE + tc + j] = acc[i][j];
}

__global__ __launch_bounds__(256) void chain_kernel(const int* __restrict__ node_i,
                                                    const int* __restrict__ node_j) {
    extern __shared__ float sm[];
    float* SA = sm;
    float* SB = sm + 128 * MSTRIDE;
    float* SC = sm + 2 * 128 * MSTRIDE;
    float* res  = sm + 3 * 128 * MSTRIDE;  // 32
    float* red  = res + 32;                // 8
    float* ebuf = red + 8;                 // 8

    const int tid = threadIdx.x;
    const int chain = blockIdx.x;
    const int b = chain & 255;
    const int li = node_i[b] - b * 128;
    const int lj = node_j[b] - b * 128;

    // load P (stride 128 -> stride 130)
    const float4* src = (const float4*)(g_P + (size_t)chain * 16384);
    for (int i = tid; i < 4096; i += 256) {
        float4 v = src[i];
        float* d = SA + (i >> 5) * MSTRIDE + ((i & 31) << 2);
        d[0] = v.x; d[1] = v.y; d[2] = v.z; d[3] = v.w;
    }
    __syncthreads();

    mm128(SA, SA, SB, tid); __syncthreads();   // P2
    mm128(SA, SB, SC, tid); __syncthreads();   // P3 = P*P2

    // ---- pass 1: k = 2,3 direct; k = 5,6 via P2/P3 pairings ----
    {
        float d2 = (tid < 128) ? SB[tid * MSTRIDE + tid] : 0.f;
        block_sum(d2, red, &res[0], tid);      // t2
        float d3 = (tid < 128) ? SC[tid * MSTRIDE + tid] : 0.f;
        block_sum(d3, red, &res[1], tid);      // t3

        int u = tid >> 1, vb = (tid & 1) * 64;
        float s5 = 0.f, s6 = 0.f;
        for (int m = 0; m < 64; m++) {
            int v = vb + m;
            float p3vu = SC[v * MSTRIDE + u];
            s5 = fmaf(SB[u * MSTRIDE + v], p3vu, s5);
            s6 = fmaf(SC[u * MSTRIDE + v], p3vu, s6);
        }
        block_sum(s5, red, &res[3], tid);      // t5 = <P2, P3^T>
        block_sum(s6, red, &res[4], tid);      // t6 = <P3, P3^T>

        int warp = tid >> 5, lane = tid & 31, p = warp & 3;
        int uu = (p == 1 || p == 3) ? lj : li;
        int vv = (p == 0) ? li : (p == 1) ? lj : (p == 2) ? lj : li;
        const float* Xm = (warp < 4) ? SB : SC;  // E5 = P2 row . P3 col ; E6 = P3 . P3
        float s = 0.f;
        #pragma unroll
        for (int q = 0; q < 4; q++) { int r = lane + q * 32; s += Xm[uu * MSTRIDE + r] * SC[r * MSTRIDE + vv]; }
        #pragma unroll
        for (int off = 16; off; off >>= 1) s += __shfl_down_sync(0xffffffffu, s, off);
        if (lane == 0) ebuf[warp] = s;
        __syncthreads();
        if (tid == 0) {
            res[7 + 3]  = ebuf[0] + ebuf[1];  res[14 + 3] = ebuf[2] + ebuf[3];  // nl5, ll5
            res[7 + 4]  = ebuf[4] + ebuf[5];  res[14 + 4] = ebuf[6] + ebuf[7];  // nl6, ll6
            res[7 + 0]  = SB[li * MSTRIDE + li] + SB[lj * MSTRIDE + lj];
            res[14 + 0] = SB[li * MSTRIDE + lj] + SB[lj * MSTRIDE + li];
            res[7 + 1]  = SC[li * MSTRIDE + li] + SC[lj * MSTRIDE + lj];
            res[14 + 1] = SC[li * MSTRIDE + lj] + SC[lj * MSTRIDE + li];
        }
        __syncthreads();
    }

    mm128(SB, SB, SA, tid); __syncthreads();   // P4 = P2*P2 (overwrites P)

    // ---- pass 2: k = 4 direct; k = 7,8 via P3/P4 pairings ----
    {
        float d4 = (tid < 128) ? SA[tid * MSTRIDE + tid] : 0.f;
        block_sum(d4, red, &res[2], tid);      // t4

        int u = tid >> 1, vb = (tid & 1) * 64;
        float s7 = 0.f, s8 = 0.f;
        for (int m = 0; m < 64; m++) {
            int v = vb + m;
            float p4vu = SA[v * MSTRIDE + u];
            s7 = fmaf(SC[u * MSTRIDE + v], p4vu, s7);
            s8 = fmaf(SA[u * MSTRIDE + v], p4vu, s8);
        }
        block_sum(s7, red, &res[5], tid);      // t7 = <P3, P4^T>
        block_sum(s8, red, &res[6], tid);      // t8 = <P4, P4^T>

        int warp = tid >> 5, lane = tid & 31, p = warp & 3;
        int uu = (p == 1 || p == 3) ? lj : li;
        int vv = (p == 0) ? li : (p == 1) ? lj : (p == 2) ? lj : li;
        const float* Xm = (warp < 4) ? SC : SA;  // E7 = P3 row . P4 col ; E8 = P4 . P4
        float s = 0.f;
        #pragma unroll
        for (int q = 0; q < 4; q++) { int r = lane + q * 32; s += Xm[uu * MSTRIDE + r] * SA[r * MSTRIDE + vv]; }
        #pragma unroll
        for (int off = 16; off; off >>= 1) s += __shfl_down_sync(0xffffffffu, s, off);
        if (lane == 0) ebuf[warp] = s;
        __syncthreads();
        if (tid == 0) {
            res[7 + 5]  = ebuf[0] + ebuf[1];  res[14 + 5] = ebuf[2] + ebuf[3];  // nl7, ll7
            res[7 + 6]  = ebuf[4] + ebuf[5];  res[14 + 6] = ebuf[6] + ebuf[7];  // nl8, ll8
            res[7 + 2]  = SA[li * MSTRIDE + li] + SA[lj * MSTRIDE + lj];
            res[14 + 2] = SA[li * MSTRIDE + lj] + SA[lj * MSTRIDE + li];
        }
        __syncthreads();
    }

    if (tid < 21) g_feats[(size_t)chain * 21 + tid] = res[tid];
}

// ============================================================================
// Kernel 3: feature assembly + MLP
// ============================================================================
__global__ void mlp_kernel(const float* __restrict__ W1, const float* __restrict__ b1,
                           const float* __restrict__ W2, const float* __restrict__ b2,
                           float* __restrict__ out) {
    const int b = blockIdx.x;
    const int t = threadIdx.x;
    __shared__ float feat[72];

    for (int s = t; s < 72; s += 32) {
        float v;
        if (s < 14) {                       // gl = trace_p - trace_m
            int h = s / 7, k = s % 7;
            v = g_feats[((size_t)(h * 256 + b)) * 21 + k]
              - g_feats[((size_t)((2 + h) * 256 + b)) * 21 + k];
        } else if (s < 16) {                // omega
            v = g_omega[b * 2 + (s - 14)];
        } else {
            int m = (s - 16) % 14;
            int blk = (s - 16) / 14;        // 0 nlp, 1 nlm, 2 llp, 3 llm
            int h = m / 7, k = m % 7;
            int sgn = blk & 1;
            int off = (blk < 2) ? 7 : 14;
            v = g_feats[((size_t)((sgn * 2 + h) * 256 + b)) * 21 + off + k];
        }
        feat[s] = v;
    }
    __syncwarp();

    float h1 = b1[t];
    #pragma unroll 8
    for (int m = 0; m < 72; m++) h1 = fmaf(feat[m], W1[m * 32 + t], h1);
    h1 = fmaxf(h1, 0.f);
    float v = h1 * W2[t];
    #pragma unroll
    for (int off = 16; off; off >>= 1) v += __shfl_down_sync(0xffffffffu, v, off);
    if (t == 0) out[b] = v + b2[0];
}

// ============================================================================
extern "C" void kernel_launch(void* const* d_in, const int* in_sizes, int n_in,
                              void* d_out, int out_size) {
    (void)in_sizes; (void)n_in; (void)out_size;
    const float* z_table = (const float*)d_in[0];
    const float* conv_W  = (const float*)d_in[1];
    const float* conv_b  = (const float*)d_in[2];
    const float* k1_W    = (const float*)d_in[3];
    const float* k1_b    = (const float*)d_in[4];
    const float* q1_W    = (const float*)d_in[5];
    const float* q1_b    = (const float*)d_in[6];
    const float* k2_W    = (const float*)d_in[7];
    const float* k2_b    = (const float*)d_in[8];
    const float* q2_W    = (const float*)d_in[9];
    const float* q2_b    = (const float*)d_in[10];
    const float* mlp_W1  = (const float*)d_in[11];
    const float* mlp_b1  = (const float*)d_in[12];
    const float* mlp_W2  = (const float*)d_in[13];
    const float* mlp_b2  = (const float*)d_in[14];
    const int*   z        = (const int*)d_in[15];
    const int*   edge_row = (const int*)d_in[16];
    const int*   edge_col = (const int*)d_in[17];
    const int*   node_i   = (const int*)d_in[20];
    const int*   node_j   = (const int*)d_in[21];
    float* out = (float*)d_out;

    cudaFuncSetAttribute(batch_kernel, cudaFuncAttributeMaxDynamicSharedMemorySize, SMB_FLOATS * 4);
    cudaFuncSetAttribute(chain_kernel, cudaFuncAttributeMaxDynamicSharedMemorySize, SMC_FLOATS * 4);

    batch_kernel<<<NB, 256, SMB_FLOATS * 4>>>(
        z_table, conv_W, conv_b, k1_W, k1_b, q1_W, q1_b,
        k2_W, k2_b, q2_W, q2_b, z, edge_row, edge_col, node_i, node_j);
    chain_kernel<<<4 * NB, 256, SMC_FLOATS * 4>>>(node_i, node_j);
    mlp_kernel<<<NB, 32>>>(mlp_W1, mlp_b1, mlp_W2, mlp_b2, out);
}

// round 3
// speedup vs baseline: 2.8181x; 2.8181x over previous
#include <cuda_runtime.h>
#include <math.h>

#define NB 256

// Compact global scratch (static; no runtime allocation)
__device__ float g_vals[(size_t)2 * 256 * 128 * 12];  // [h][b][c]{ews0..7, ec, invp, invm, pad}
__device__ uint2 g_rows[256 * 128];                   // [b][c] 8 packed row bytes
__device__ float g_feats[4 * NB * 21];                // per chain: t2..8, nl2..8, ll2..8
__device__ float g_omega[NB * 2];

// ============================================================================
// Kernel 1: per-batch GCN (sparse agg) + attention -> compact softmax rep
// smem floats: X 0(4096) XW 4096(4096) Q2 8192(8192,str64) K2 16384(8192)
//   Wb 24576(2048) dinv 26624(128) wcs 26752(4) zloc 26756(128i) rows 26884(1024i)
// ============================================================================
#define SMB_FLOATS 27908

__global__ __launch_bounds__(256) void batch_kernel(
    const float* __restrict__ z_table, const float* __restrict__ conv_W, const float* __restrict__ conv_b,
    const float* __restrict__ k1_W, const float* __restrict__ k1_b,
    const float* __restrict__ q1_W, const float* __restrict__ q1_b,
    const float* __restrict__ k2_W, const float* __restrict__ k2_b,
    const float* __restrict__ q2_W, const float* __restrict__ q2_b,
    const int* __restrict__ z, const int* __restrict__ edge_row,
    const int* __restrict__ node_i, const int* __restrict__ node_j)
{
    extern __shared__ float sm[];
    float* X    = sm;
    float* XW   = sm + 4096;
    float* Q2   = sm + 8192;     // stride 64
    float* K2   = sm + 16384;    // stride 64
    float* Wb   = sm + 24576;
    float* dinv = sm + 26624;
    float* wcs  = sm + 26752;
    int*   zloc = (int*)(sm + 26756);
    int*   rows = (int*)(sm + 26884);  // [c][k]

    const int tid   = threadIdx.x;
    const int b     = blockIdx.x;
    const int gbase = b * 128;
    const int ebase = b * 1024;
    const int li    = node_i[b] - gbase;
    const int lj    = node_j[b] - gbase;

    if (tid < 128) {
        float dg = 9.f + (tid == li ? 1.f : 0.f) + (tid == lj ? 1.f : 0.f);
        dinv[tid] = rsqrtf(dg);
        zloc[tid] = z[gbase + tid];
    }
    for (int e = tid; e < 1024; e += 256)
        rows[(e & 127) * 8 + (e >> 7)] = edge_row[ebase + e] - gbase;
    __syncthreads();

    for (int i = tid; i < 4096; i += 256)
        X[i] = z_table[zloc[i >> 5] * 32 + (i & 31)];
    __syncthreads();

    const int warp = tid >> 5, lane = tid & 31;

    // 3 GCN layers: X <- act( sparse-agg( X @ W_l ) + b_l )
    for (int l = 0; l < 3; ++l) {
        for (int i = tid; i < 1024; i += 256) Wb[i] = conv_W[l * 1024 + i];
        __syncthreads();
        for (int i = tid; i < 4096; i += 256) {
            int r = i >> 5, f = i & 31;
            float s = 0.f;
            #pragma unroll 8
            for (int m = 0; m < 32; ++m) s = fmaf(X[r * 32 + m], Wb[m * 32 + f], s);
            XW[i] = s;
        }
        __syncthreads();
        for (int it = 0; it < 16; ++it) {
            int c = it * 8 + warp;
            float dc = dinv[c];
            float acc = conv_b[l * 32 + lane] + dc * dc * XW[c * 32 + lane];
            #pragma unroll
            for (int k = 0; k < 8; ++k) {
                int r = rows[c * 8 + k];
                acc = fmaf(dinv[r] * dc, XW[r * 32 + lane], acc);
            }
            if (c == li)      acc = fmaf(dinv[lj] * dc, XW[lj * 32 + lane], acc);
            else if (c == lj) acc = fmaf(dinv[li] * dc, XW[li * 32 + lane], acc);
            X[c * 32 + lane] = (l < 2) ? fmaxf(acc, 0.f) : acc;
        }
        __syncthreads();
    }

    // Q path: Q2 = (leaky(X@k1_W+k1_b)) @ k2_W + k2_b   (used at edge ROWS)
    for (int i = tid; i < 1024; i += 256) Wb[i] = k1_W[i];
    __syncthreads();
    for (int i = tid; i < 4096; i += 256) {
        int r = i >> 5, f = i & 31;
        float s = k1_b[f];
        #pragma unroll 8
        for (int m = 0; m < 32; ++m) s = fmaf(X[r * 32 + m], Wb[m * 32 + f], s);
        XW[i] = (s > 0.f) ? s : 0.2f * s;
    }
    __syncthreads();
    for (int i = tid; i < 2048; i += 256) Wb[i] = k2_W[i];
    __syncthreads();
    for (int i = tid; i < 8192; i += 256) {
        int r = i >> 6, f = i & 63;
        float s = k2_b[f];
        #pragma unroll 8
        for (int m = 0; m < 32; ++m) s = fmaf(XW[r * 32 + m], Wb[m * 64 + f], s);
        Q2[i] = s;
    }
    __syncthreads();
    // K path
    for (int i = tid; i < 1024; i += 256) Wb[i] = q1_W[i];
    __syncthreads();
    for (int i = tid; i < 4096; i += 256) {
        int r = i >> 5, f = i & 31;
        float s = q1_b[f];
        #pragma unroll 8
        for (int m = 0; m < 32; ++m) s = fmaf(X[r * 32 + m], Wb[m * 32 + f], s);
        XW[i] = (s > 0.f) ? s : 0.2f * s;
    }
    __syncthreads();
    for (int i = tid; i < 2048; i += 256) Wb[i] = q2_W[i];
    __syncthreads();
    for (int i = tid; i < 8192; i += 256) {
        int r = i >> 6, f = i & 63;
        float s = q2_b[f];
        #pragma unroll 8
        for (int m = 0; m < 32; ++m) s = fmaf(XW[r * 32 + m], Wb[m * 64 + f], s);
        K2[i] = s;
    }
    __syncthreads();

    // Attention per (col c, head h): logits + segment softmax -> compact rep
    const int c = tid & 127;
    const int h = tid >> 7;
    const float isq = 0.17677669529663687f;  // 1/sqrt(32)

    float kv[32];
    #pragma unroll
    for (int f = 0; f < 32; ++f) kv[f] = K2[c * 64 + h * 32 + f];

    float w[8];
    int rws[8];
    #pragma unroll
    for (int k = 0; k < 8; ++k) {
        int r = rows[c * 8 + k];
        rws[k] = r;
        float s = 0.f;
        #pragma unroll 8
        for (int f = 0; f < 32; ++f) s = fmaf(Q2[r * 64 + h * 32 + f], kv[f], s);
        w[k] = s * isq;
    }
    bool cand = (c == li) || (c == lj);
    float w8 = 0.f;
    if (cand) {
        int r = (c == li) ? lj : li;
        float s = 0.f;
        #pragma unroll 8
        for (int f = 0; f < 32; ++f) s = fmaf(Q2[r * 64 + h * 32 + f], kv[f], s);
        w8 = s * isq;
        wcs[h * 2 + (c == li ? 1 : 0)] = 1.f / (1.f + expf(-w8));
    }
    float wmax = w[0];
    #pragma unroll
    for (int k = 1; k < 8; ++k) wmax = fmaxf(wmax, w[k]);
    if (cand) wmax = fmaxf(wmax, w8);

    float ews[8];
    float sum8 = 0.f;
    #pragma unroll
    for (int k = 0; k < 8; ++k) { ews[k] = expf(w[k] - wmax); sum8 += ews[k]; }
    float ec = cand ? expf(w8 - wmax) : 0.f;
    float invp = 1.f / (sum8 + ec + 1e-16f);
    float invm = 1.f / (sum8 + 1e-16f);

    size_t vb = (((size_t)h * 256 + b) * 128 + c) * 12;
    *(float4*)(g_vals + vb)     = make_float4(ews[0], ews[1], ews[2], ews[3]);
    *(float4*)(g_vals + vb + 4) = make_float4(ews[4], ews[5], ews[6], ews[7]);
    *(float4*)(g_vals + vb + 8) = make_float4(ec, invp, invm, 0.f);
    if (h == 0) {
        uint2 pk;
        pk.x = (unsigned)rws[0] | ((unsigned)rws[1] << 8) | ((unsigned)rws[2] << 16) | ((unsigned)rws[3] << 24);
        pk.y = (unsigned)rws[4] | ((unsigned)rws[5] << 8) | ((unsigned)rws[6] << 16) | ((unsigned)rws[7] << 24);
        g_rows[b * 128 + c] = pk;
    }
    __syncthreads();
    if (tid < 2) g_omega[b * 2 + tid] = wcs[tid * 2] + wcs[tid * 2 + 1];
}

// ============================================================================
// Kernel 2: per-chain sparse matrix powers + feature extraction
// chain id: sign = bid>>9 (0=p,1=m), h = (bid>>8)&1, b = bid&255
// smem floats: A 0(16384) Bm 16384(16384) sv 32768(1280) sr 34048(1280i)
//   scnt 35328(128i) colb 35456(512) res 35968(32) red 36000(16) ebuf 36016(16)
// ============================================================================
#define CT 512
#define SMC_FLOATS 36032

__device__ __forceinline__ void block_sum16(float v, float* red, float* slot, int tid) {
    #pragma unroll
    for (int off = 16; off; off >>= 1) v += __shfl_down_sync(0xffffffffu, v, off);
    if ((tid & 31) == 0) red[tid >> 5] = v;
    __syncthreads();
    if (tid == 0) {
        float s = red[0];
        #pragma unroll
        for (int ww = 1; ww < 16; ++ww) s += red[ww];
        *slot = s;
    }
    __syncthreads();
}

// Out = T(sparse) * In : row c of Out = sum_k val_k(c) * row rws_k(c) of In
__device__ __forceinline__ void spstep(const float* __restrict__ In, float* __restrict__ Out,
                                       const float* __restrict__ sv, const int* __restrict__ sr,
                                       const int* __restrict__ scnt, int warp, int lane) {
    for (int it = 0; it < 8; ++it) {
        int c = it * 16 + warp;
        int cnt = scnt[c];
        float4 acc = make_float4(0.f, 0.f, 0.f, 0.f);
        for (int k = 0; k < cnt; ++k) {
            float v = sv[c * 10 + k];
            int r = sr[c * 10 + k];
            float4 x = *(const float4*)(In + r * 128 + lane * 4);
            acc.x = fmaf(v, x.x, acc.x);
            acc.y = fmaf(v, x.y, acc.y);
            acc.z = fmaf(v, x.z, acc.z);
            acc.w = fmaf(v, x.w, acc.w);
        }
        *(float4*)(Out + c * 128 + lane * 4) = acc;
    }
}

__global__ __launch_bounds__(CT) void chain_kernel(const int* __restrict__ node_i,
                                                   const int* __restrict__ node_j) {
    extern __shared__ float sm[];
    float* A    = sm;            // T2, later T4
    float* Bm   = sm + 16384;    // T3
    float* sv   = sm + 32768;    // [128][10]
    int*   sr   = (int*)(sm + 34048);
    int*   scnt = (int*)(sm + 35328);
    float* colb = sm + 35456;    // 4 x 128: T3col_li, T3col_lj, T4col_li, T4col_lj
    float* res  = sm + 35968;
    float* red  = sm + 36000;
    float* ebuf = sm + 36016;

    const int tid  = threadIdx.x;
    const int bid  = blockIdx.x;
    const int sign = bid >> 9;
    const int h    = (bid >> 8) & 1;
    const int b    = bid & 255;
    const int li   = node_i[b] - b * 128;
    const int lj   = node_j[b] - b * 128;
    const int warp = tid >> 5, lane = tid & 31;

    // Build sparse rep for this chain
    if (tid < 128) {
        int c = tid;
        uint2 pr = g_rows[b * 128 + c];
        const float4* gv = (const float4*)(g_vals + (((size_t)h * 256 + b) * 128 + c) * 12);
        float4 v0 = gv[0], v1 = gv[1], v2 = gv[2];
        float inv = (sign == 0) ? v2.y : v2.z;
        float ev[8] = {v0.x, v0.y, v0.z, v0.w, v1.x, v1.y, v1.z, v1.w};
        #pragma unroll
        for (int k = 0; k < 4; ++k) {
            sr[c * 10 + k]     = (pr.x >> (8 * k)) & 255;
            sr[c * 10 + 4 + k] = (pr.y >> (8 * k)) & 255;
        }
        #pragma unroll
        for (int k = 0; k < 8; ++k) sv[c * 10 + k] = ev[k] * inv;
        int n = 8;
        if (sign == 0 && (c == li || c == lj)) {
            sr[c * 10 + 8] = (c == li) ? lj : li;
            sv[c * 10 + 8] = v2.x * inv;
            n = 9;
        }
        scnt[c] = n;
    }
    for (int i = tid; i < 4096; i += CT)
        *(float4*)(A + i * 4) = make_float4(0.f, 0.f, 0.f, 0.f);
    __syncthreads();

    // T2 via sparse x sparse scatter (thread per row)
    if (tid < 128) {
        int c = tid, n = scnt[c];
        for (int k = 0; k < n; ++k) {
            float v = sv[c * 10 + k];
            int r = sr[c * 10 + k];
            int nr = scnt[r];
            for (int j = 0; j < nr; ++j)
                A[c * 128 + sr[r * 10 + j]] += v * sv[r * 10 + j];
        }
    }
    __syncthreads();

    // t2 + k=2 entries (from T2 in A)
    block_sum16((tid < 128) ? A[tid * 129] : 0.f, red, &res[0], tid);
    if (tid == 0) {
        res[7]  = A[li * 129] + A[lj * 129];
        res[14] = A[li * 128 + lj] + A[lj * 128 + li];
    }

    spstep(A, Bm, sv, sr, scnt, warp, lane);   // T3 = T * T2
    __syncthreads();

    block_sum16((tid < 128) ? Bm[tid * 129] : 0.f, red, &res[1], tid);  // t3
    if (tid == 0) {
        res[8]  = Bm[li * 129] + Bm[lj * 129];
        res[15] = Bm[li * 128 + lj] + Bm[lj * 128 + li];
    }
    __syncthreads();                            // all T2 reads done

    spstep(Bm, A, sv, sr, scnt, warp, lane);   // T4 = T * T3 (overwrites T2)
    __syncthreads();

    block_sum16((tid < 128) ? A[tid * 129] : 0.f, red, &res[2], tid);   // t4
    if (tid == 0) {
        res[9]  = A[li * 129] + A[lj * 129];
        res[16] = A[li * 128 + lj] + A[lj * 128 + li];
    }

    // t5 = tr(T * T4) via sparse rep
    {
        float s5 = 0.f;
        if (tid < 128) {
            int n = scnt[tid];
            for (int k = 0; k < n; ++k)
                s5 = fmaf(sv[tid * 10 + k], A[sr[tid * 10 + k] * 128 + tid], s5);
        }
        block_sum16(s5, red, &res[3], tid);
    }

    // t6 = <T3,T3^T>, t7 = <T3,T4^T>, t8 = <T4,T4^T> — diagonal walk, conflict-free
    {
        float t6 = 0.f, t7 = 0.f, t8 = 0.f;
        for (int s = 0; s < 32; ++s) {
            int g = s * CT + tid;
            int a = g & 127, d = g >> 7;
            int b2 = (a + d) & 127;
            float x3ab = Bm[a * 128 + b2], x3ba = Bm[b2 * 128 + a];
            float x4ab = A[a * 128 + b2],  x4ba = A[b2 * 128 + a];
            t6 = fmaf(x3ab, x3ba, t6);
            t7 = fmaf(x3ab, x4ba, t7);
            t8 = fmaf(x4ab, x4ba, t8);
        }
        block_sum16(t6, red, &res[4], tid);
        block_sum16(t7, red, &res[5], tid);
        block_sum16(t8, red, &res[6], tid);
    }

    // k=5 entries: T5[u,v] = sum_k val_k(u) * T4[rws_k(u), v]
    if (tid == 0) {
        float eii = 0.f, eij = 0.f, eji = 0.f, ejj = 0.f;
        int ni = scnt[li];
        for (int k = 0; k < ni; ++k) {
            float v = sv[li * 10 + k]; int r = sr[li * 10 + k];
            eii = fmaf(v, A[r * 128 + li], eii);
            eij = fmaf(v, A[r * 128 + lj], eij);
        }
        int nj = scnt[lj];
        for (int k = 0; k < nj; ++k) {
            float v = sv[lj * 10 + k]; int r = sr[lj * 10 + k];
            eji = fmaf(v, A[r * 128 + li], eji);
            ejj = fmaf(v, A[r * 128 + lj], ejj);
        }
        res[10] = eii + ejj;   // nl5
        res[17] = eij + eji;   // ll5
    }

    // extract columns li/lj of T3 and T4
    {
        int w = tid >> 7, m = tid & 127;
        const float* M = (w < 2) ? Bm : A;
        int v = (w & 1) ? lj : li;
        colb[w * 128 + m] = M[m * 128 + v];
    }
    __syncthreads();

    // 12 row.col dots for k = 6,7,8 entries
    if (warp < 12) {
        const float* R; int u; const float* C;
        if (warp < 4)      { R = Bm; u = (warp < 2) ? li : lj; C = colb + (warp & 1) * 128; }
        else if (warp < 8) { R = Bm; u = (warp < 6) ? li : lj; C = colb + (2 + (warp & 1)) * 128; }
        else               { R = A;  u = (warp < 10) ? li : lj; C = colb + (2 + (warp & 1)) * 128; }
        float s = 0.f;
        #pragma unroll
        for (int q = 0; q < 4; ++q) { int m = lane + 32 * q; s = fmaf(R[u * 128 + m], C[m], s); }
        #pragma unroll
        for (int off = 16; off; off >>= 1) s += __shfl_down_sync(0xffffffffu, s, off);
        if (lane == 0) ebuf[warp] = s;
    }
    __syncthreads();
    if (tid == 0) {
        res[11] = ebuf[0] + ebuf[3];   res[18] = ebuf[1] + ebuf[2];    // nl6, ll6
        res[12] = ebuf[4] + ebuf[7];   res[19] = ebuf[5] + ebuf[6];    // nl7, ll7
        res[13] = ebuf[8] + ebuf[11];  res[20] = ebuf[9] + ebuf[10];   // nl8, ll8
    }
    __syncthreads();
    if (tid < 21) g_feats[(size_t)bid * 21 + tid] = res[tid];
}

// ============================================================================
// Kernel 3: feature assembly + MLP
// ============================================================================
__global__ void mlp_kernel(const float* __restrict__ W1, const float* __restrict__ b1,
                           const float* __restrict__ W2, const float* __restrict__ b2,
                           float* __restrict__ out) {
    const int b = blockIdx.x;
    const int t = threadIdx.x;
    __shared__ float feat[72];

    for (int s = t; s < 72; s += 32) {
        float v;
        if (s < 14) {                       // gl = trace_p - trace_m
            int h = s / 7, k = s % 7;
            v = g_feats[((size_t)(h * 256 + b)) * 21 + k]
              - g_feats[((size_t)((2 + h) * 256 + b)) * 21 + k];
        } else if (s < 16) {                // omega
            v = g_omega[b * 2 + (s - 14)];
        } else {
            int m = (s - 16) % 14;
            int blk = (s - 16) / 14;        // 0 nlp, 1 nlm, 2 llp, 3 llm
            int h = m / 7, k = m % 7;
            int sgn = blk & 1;
            int off = (blk < 2) ? 7 : 14;
            v = g_feats[((size_t)((sgn * 2 + h) * 256 + b)) * 21 + off + k];
        }
        feat[s] = v;
    }
    __syncwarp();

    float h1 = b1[t];
    #pragma unroll 8
    for (int m = 0; m < 72; ++m) h1 = fmaf(feat[m], W1[m * 32 + t], h1);
    h1 = fmaxf(h1, 0.f);
    float v = h1 * W2[t];
    #pragma unroll
    for (int off = 16; off; off >>= 1) v += __shfl_down_sync(0xffffffffu, v, off);
    if (t == 0) out[b] = v + b2[0];
}

// ============================================================================
extern "C" void kernel_launch(void* const* d_in, const int* in_sizes, int n_in,
                              void* d_out, int out_size) {
    (void)in_sizes; (void)n_in; (void)out_size;
    const float* z_table = (const float*)d_in[0];
    const float* conv_W  = (const float*)d_in[1];
    const float* conv_b  = (const float*)d_in[2];
    const float* k1_W    = (const float*)d_in[3];
    const float* k1_b    = (const float*)d_in[4];
    const float* q1_W    = (const float*)d_in[5];
    const float* q1_b    = (const float*)d_in[6];
    const float* k2_W    = (const float*)d_in[7];
    const float* k2_b    = (const float*)d_in[8];
    const float* q2_W    = (const float*)d_in[9];
    const float* q2_b    = (const float*)d_in[10];
    const float* mlp_W1  = (const float*)d_in[11];
    const float* mlp_b1  = (const float*)d_in[12];
    const float* mlp_W2  = (const float*)d_in[13];
    const float* mlp_b2  = (const float*)d_in[14];
    const int*   z        = (const int*)d_in[15];
    const int*   edge_row = (const int*)d_in[16];
    const int*   node_i   = (const int*)d_in[20];
    const int*   node_j   = (const int*)d_in[21];
    float* out = (float*)d_out;

    cudaFuncSetAttribute(batch_kernel, cudaFuncAttributeMaxDynamicSharedMemorySize, SMB_FLOATS * 4);
    cudaFuncSetAttribute(chain_kernel, cudaFuncAttributeMaxDynamicSharedMemorySize, SMC_FLOATS * 4);

    batch_kernel<<<NB, 256, SMB_FLOATS * 4>>>(
        z_table, conv_W, conv_b, k1_W, k1_b, q1_W, q1_b,
        k2_W, k2_b, q2_W, q2_b, z, edge_row, node_i, node_j);
    chain_kernel<<<4 * NB, CT, SMC_FLOATS * 4>>>(node_i, node_j);
    mlp_kernel<<<NB, 32>>>(mlp_W1, mlp_b1, mlp_W2, mlp_b2, out);
}

// round 4
// speedup vs baseline: 3.0633x; 1.0870x over previous
#include <cuda_runtime.h>
#include <math.h>

#define NB 256

// Compact global scratch (static; no runtime allocation)
__device__ float g_vals[(size_t)2 * 256 * 128 * 12];  // [h][b][c]{ews0..7, ec, invp, invm, pad}
__device__ uint2 g_rows[256 * 128];                   // [b][c] 8 packed row bytes
__device__ float g_feats[4 * NB * 21];                // per chain: t2..8, nl2..8, ll2..8
__device__ float g_omega[NB * 2];

// ============================================================================
// Kernel 1: per-batch GCN (sparse agg) + attention -> compact softmax rep
// smem floats: X 0(4096) XW 4096(4096) Q2 8192(8320,str65) K2 16512(8320)
//   Wb 24832(2048) dinv 26880(128) wcs 27008(4) zloc 27012(128i) rows 27140(1024i)
// ============================================================================
#define SMB_FLOATS 28164

__global__ __launch_bounds__(256, 2) void batch_kernel(
    const float* __restrict__ z_table, const float* __restrict__ conv_W, const float* __restrict__ conv_b,
    const float* __restrict__ k1_W, const float* __restrict__ k1_b,
    const float* __restrict__ q1_W, const float* __restrict__ q1_b,
    const float* __restrict__ k2_W, const float* __restrict__ k2_b,
    const float* __restrict__ q2_W, const float* __restrict__ q2_b,
    const int* __restrict__ z, const int* __restrict__ edge_row,
    const int* __restrict__ node_i, const int* __restrict__ node_j)
{
    extern __shared__ float sm[];
    float* X    = sm;
    float* XW   = sm + 4096;
    float* Q2   = sm + 8192;     // stride 65
    float* K2   = sm + 16512;    // stride 65
    float* Wb   = sm + 24832;
    float* dinv = sm + 26880;
    float* wcs  = sm + 27008;
    int*   zloc = (int*)(sm + 27012);
    int*   rows = (int*)(sm + 27140);  // [c][k]

    const int tid   = threadIdx.x;
    const int b     = blockIdx.x;
    const int gbase = b * 128;
    const int ebase = b * 1024;
    const int li    = node_i[b] - gbase;
    const int lj    = node_j[b] - gbase;

    if (tid < 128) {
        float dg = 9.f + (tid == li ? 1.f : 0.f) + (tid == lj ? 1.f : 0.f);
        dinv[tid] = rsqrtf(dg);
        zloc[tid] = z[gbase + tid];
    }
    for (int e = tid; e < 1024; e += 256)
        rows[(e & 127) * 8 + (e >> 7)] = edge_row[ebase + e] - gbase;
    __syncthreads();

    for (int i = tid; i < 4096; i += 256)
        X[i] = z_table[zloc[i >> 5] * 32 + (i & 31)];
    __syncthreads();

    const int warp = tid >> 5, lane = tid & 31;

    // 3 GCN layers: X <- act( sparse-agg( X @ W_l ) + b_l )
    for (int l = 0; l < 3; ++l) {
        for (int i = tid; i < 1024; i += 256) Wb[i] = conv_W[l * 1024 + i];
        __syncthreads();
        #pragma unroll
        for (int g = 0; g < 4; ++g) {
            int i = tid + g * 256;
            int r = i >> 3, f4 = (i & 7) * 4;
            float4 acc = make_float4(0.f, 0.f, 0.f, 0.f);
            #pragma unroll
            for (int m = 0; m < 32; ++m) {
                float a = X[r * 32 + m];
                float4 w4 = *(const float4*)(Wb + m * 32 + f4);
                acc.x = fmaf(a, w4.x, acc.x); acc.y = fmaf(a, w4.y, acc.y);
                acc.z = fmaf(a, w4.z, acc.z); acc.w = fmaf(a, w4.w, acc.w);
            }
            *(float4*)(XW + r * 32 + f4) = acc;
        }
        __syncthreads();
        for (int it = 0; it < 16; ++it) {
            int c = it * 8 + warp;
            float dc = dinv[c];
            float acc = conv_b[l * 32 + lane] + dc * dc * XW[c * 32 + lane];
            #pragma unroll
            for (int k = 0; k < 8; ++k) {
                int r = rows[c * 8 + k];
                acc = fmaf(dinv[r] * dc, XW[r * 32 + lane], acc);
            }
            if (c == li)      acc = fmaf(dinv[lj] * dc, XW[lj * 32 + lane], acc);
            else if (c == lj) acc = fmaf(dinv[li] * dc, XW[li * 32 + lane], acc);
            X[c * 32 + lane] = (l < 2) ? fmaxf(acc, 0.f) : acc;
        }
        __syncthreads();
    }

    // Q path: Q2 = (leaky(X@k1_W+k1_b)) @ k2_W + k2_b   (used at edge ROWS)
    for (int i = tid; i < 1024; i += 256) Wb[i] = k1_W[i];
    __syncthreads();
    #pragma unroll
    for (int g = 0; g < 4; ++g) {
        int i = tid + g * 256;
        int r = i >> 3, f4 = (i & 7) * 4;
        float4 acc = *(const float4*)(k1_b + f4);
        #pragma unroll
        for (int m = 0; m < 32; ++m) {
            float a = X[r * 32 + m];
            float4 w4 = *(const float4*)(Wb + m * 32 + f4);
            acc.x = fmaf(a, w4.x, acc.x); acc.y = fmaf(a, w4.y, acc.y);
            acc.z = fmaf(a, w4.z, acc.z); acc.w = fmaf(a, w4.w, acc.w);
        }
        acc.x = (acc.x > 0.f) ? acc.x : 0.2f * acc.x;
        acc.y = (acc.y > 0.f) ? acc.y : 0.2f * acc.y;
        acc.z = (acc.z > 0.f) ? acc.z : 0.2f * acc.z;
        acc.w = (acc.w > 0.f) ? acc.w : 0.2f * acc.w;
        *(float4*)(XW + r * 32 + f4) = acc;
    }
    __syncthreads();
    for (int i = tid; i < 2048; i += 256) Wb[i] = k2_W[i];
    __syncthreads();
    #pragma unroll
    for (int g = 0; g < 8; ++g) {
        int i = tid + g * 256;
        int r = i >> 4, f4 = (i & 15) * 4;
        float4 acc = *(const float4*)(k2_b + f4);
        #pragma unroll
        for (int m = 0; m < 32; ++m) {
            float a = XW[r * 32 + m];
            float4 w4 = *(const float4*)(Wb + m * 64 + f4);
            acc.x = fmaf(a, w4.x, acc.x); acc.y = fmaf(a, w4.y, acc.y);
            acc.z = fmaf(a, w4.z, acc.z); acc.w = fmaf(a, w4.w, acc.w);
        }
        float* dst = Q2 + r * 65 + f4;
        dst[0] = acc.x; dst[1] = acc.y; dst[2] = acc.z; dst[3] = acc.w;
    }
    __syncthreads();
    // K path
    for (int i = tid; i < 1024; i += 256) Wb[i] = q1_W[i];
    __syncthreads();
    #pragma unroll
    for (int g = 0; g < 4; ++g) {
        int i = tid + g * 256;
        int r = i >> 3, f4 = (i & 7) * 4;
        float4 acc = *(const float4*)(q1_b + f4);
        #pragma unroll
        for (int m = 0; m < 32; ++m) {
            float a = X[r * 32 + m];
            float4 w4 = *(const float4*)(Wb + m * 32 + f4);
            acc.x = fmaf(a, w4.x, acc.x); acc.y = fmaf(a, w4.y, acc.y);
            acc.z = fmaf(a, w4.z, acc.z); acc.w = fmaf(a, w4.w, acc.w);
        }
        acc.x = (acc.x > 0.f) ? acc.x : 0.2f * acc.x;
        acc.y = (acc.y > 0.f) ? acc.y : 0.2f * acc.y;
        acc.z = (acc.z > 0.f) ? acc.z : 0.2f * acc.z;
        acc.w = (acc.w > 0.f) ? acc.w : 0.2f * acc.w;
        *(float4*)(XW + r * 32 + f4) = acc;
    }
    __syncthreads();
    for (int i = tid; i < 2048; i += 256) Wb[i] = q2_W[i];
    __syncthreads();
    #pragma unroll
    for (int g = 0; g < 8; ++g) {
        int i = tid + g * 256;
        int r = i >> 4, f4 = (i & 15) * 4;
        float4 acc = *(const float4*)(q2_b + f4);
        #pragma unroll
        for (int m = 0; m < 32; ++m) {
            float a = XW[r * 32 + m];
            float4 w4 = *(const float4*)(Wb + m * 64 + f4);
            acc.x = fmaf(a, w4.x, acc.x); acc.y = fmaf(a, w4.y, acc.y);
            acc.z = fmaf(a, w4.z, acc.z); acc.w = fmaf(a, w4.w, acc.w);
        }
        float* dst = K2 + r * 65 + f4;
        dst[0] = acc.x; dst[1] = acc.y; dst[2] = acc.z; dst[3] = acc.w;
    }
    __syncthreads();

    // Attention per (col c, head h): logits + segment softmax -> compact rep
    const int c = tid & 127;
    const int h = tid >> 7;
    const float isq = 0.17677669529663687f;  // 1/sqrt(32)

    float kv[32];
    #pragma unroll
    for (int f = 0; f < 32; ++f) kv[f] = K2[c * 65 + h * 32 + f];

    float w[8];
    int rws[8];
    #pragma unroll
    for (int k = 0; k < 8; ++k) {
        int r = rows[c * 8 + k];
        rws[k] = r;
        float s = 0.f;
        #pragma unroll 8
        for (int f = 0; f < 32; ++f) s = fmaf(Q2[r * 65 + h * 32 + f], kv[f], s);
        w[k] = s * isq;
    }
    bool cand = (c == li) || (c == lj);
    float w8 = 0.f;
    if (cand) {
        int r = (c == li) ? lj : li;
        float s = 0.f;
        #pragma unroll 8
        for (int f = 0; f < 32; ++f) s = fmaf(Q2[r * 65 + h * 32 + f], kv[f], s);
        w8 = s * isq;
        wcs[h * 2 + (c == li ? 1 : 0)] = 1.f / (1.f + expf(-w8));
    }
    float wmax = w[0];
    #pragma unroll
    for (int k = 1; k < 8; ++k) wmax = fmaxf(wmax, w[k]);
    if (cand) wmax = fmaxf(wmax, w8);

    float ews[8];
    float sum8 = 0.f;
    #pragma unroll
    for (int k = 0; k < 8; ++k) { ews[k] = expf(w[k] - wmax); sum8 += ews[k]; }
    float ec = cand ? expf(w8 - wmax) : 0.f;
    float invp = 1.f / (sum8 + ec + 1e-16f);
    float invm = 1.f / (sum8 + 1e-16f);

    size_t vb = (((size_t)h * 256 + b) * 128 + c) * 12;
    *(float4*)(g_vals + vb)     = make_float4(ews[0], ews[1], ews[2], ews[3]);
    *(float4*)(g_vals + vb + 4) = make_float4(ews[4], ews[5], ews[6], ews[7]);
    *(float4*)(g_vals + vb + 8) = make_float4(ec, invp, invm, 0.f);
    if (h == 0) {
        uint2 pk;
        pk.x = (unsigned)rws[0] | ((unsigned)rws[1] << 8) | ((unsigned)rws[2] << 16) | ((unsigned)rws[3] << 24);
        pk.y = (unsigned)rws[4] | ((unsigned)rws[5] << 8) | ((unsigned)rws[6] << 16) | ((unsigned)rws[7] << 24);
        g_rows[b * 128 + c] = pk;
    }
    __syncthreads();
    if (tid < 2) g_omega[b * 2 + tid] = wcs[tid * 2] + wcs[tid * 2 + 1];
}

// ============================================================================
// Kernel 2: per-chain sparse matrix powers + feature extraction
// chain id: sign = bid>>9 (0=p,1=m), h = (bid>>8)&1, b = bid&255
// Fixed 9 sparse slots per row (slot padded with v=0, r=0 when absent).
// ============================================================================
#define CT 512
#define SMC_FLOATS 35936

__device__ __forceinline__ void block_sum16(float v, float* red, float* slot, int tid) {
    #pragma unroll
    for (int off = 16; off; off >>= 1) v += __shfl_down_sync(0xffffffffu, v, off);
    if ((tid & 31) == 0) red[tid >> 5] = v;
    __syncthreads();
    if (tid == 0) {
        float s = red[0];
        #pragma unroll
        for (int ww = 1; ww < 16; ++ww) s += red[ww];
        *slot = s;
    }
    __syncthreads();
}

__device__ __forceinline__ void block_sum3(float v0, float v1, float v2, float* red,
                                           float* s0, float* s1, float* s2, int tid) {
    #pragma unroll
    for (int off = 16; off; off >>= 1) {
        v0 += __shfl_down_sync(0xffffffffu, v0, off);
        v1 += __shfl_down_sync(0xffffffffu, v1, off);
        v2 += __shfl_down_sync(0xffffffffu, v2, off);
    }
    if ((tid & 31) == 0) {
        red[tid >> 5] = v0; red[16 + (tid >> 5)] = v1; red[32 + (tid >> 5)] = v2;
    }
    __syncthreads();
    if (tid == 0) {
        float a = 0.f, b = 0.f, c = 0.f;
        #pragma unroll
        for (int ww = 0; ww < 16; ++ww) { a += red[ww]; b += red[16 + ww]; c += red[32 + ww]; }
        *s0 = a; *s1 = b; *s2 = c;
    }
    __syncthreads();
}

// Out = T(sparse, fixed 9) * In : row c of Out = sum_k v_k(c) * row r_k(c) of In
__device__ __forceinline__ void spstep(const float* __restrict__ In, float* __restrict__ Out,
                                       const float* __restrict__ sv, const int* __restrict__ sr,
                                       int warp, int lane) {
    const float4* In4 = (const float4*)In;
    #pragma unroll
    for (int it = 0; it < 8; ++it) {
        int c = it * 16 + warp;
        float v[9]; int r[9];
        #pragma unroll
        for (int k = 0; k < 9; ++k) { v[k] = sv[c * 10 + k]; r[k] = sr[c * 10 + k]; }
        float4 acc = make_float4(0.f, 0.f, 0.f, 0.f);
        #pragma unroll
        for (int k = 0; k < 9; ++k) {
            float4 x = In4[r[k] * 32 + lane];
            acc.x = fmaf(v[k], x.x, acc.x);
            acc.y = fmaf(v[k], x.y, acc.y);
            acc.z = fmaf(v[k], x.z, acc.z);
            acc.w = fmaf(v[k], x.w, acc.w);
        }
        *(float4*)(Out + c * 128 + lane * 4) = acc;
    }
}

__global__ __launch_bounds__(CT) void chain_kernel(const int* __restrict__ node_i,
                                                   const int* __restrict__ node_j) {
    extern __shared__ float sm[];
    float* A    = sm;            // T2, later T4
    float* Bm   = sm + 16384;    // T3
    float* sv   = sm + 32768;    // [128][10]
    int*   sr   = (int*)(sm + 34048);
    float* colb = sm + 35328;    // 4 x 128
    float* res  = sm + 35840;    // 32
    float* red  = sm + 35872;    // 48
    float* ebuf = sm + 35920;    // 16

    const int tid  = threadIdx.x;
    const int bid  = blockIdx.x;
    const int sign = bid >> 9;
    const int h    = (bid >> 8) & 1;
    const int b    = bid & 255;
    const int li   = node_i[b] - b * 128;
    const int lj   = node_j[b] - b * 128;
    const int warp = tid >> 5, lane = tid & 31;

    // Build sparse rep for this chain (fixed 9 slots)
    if (tid < 128) {
        int c = tid;
        uint2 pr = g_rows[b * 128 + c];
        const float4* gv = (const float4*)(g_vals + (((size_t)h * 256 + b) * 128 + c) * 12);
        float4 v0 = gv[0], v1 = gv[1], v2 = gv[2];
        float inv = (sign == 0) ? v2.y : v2.z;
        float ev[8] = {v0.x, v0.y, v0.z, v0.w, v1.x, v1.y, v1.z, v1.w};
        #pragma unroll
        for (int k = 0; k < 4; ++k) {
            sr[c * 10 + k]     = (pr.x >> (8 * k)) & 255;
            sr[c * 10 + 4 + k] = (pr.y >> (8 * k)) & 255;
        }
        #pragma unroll
        for (int k = 0; k < 8; ++k) sv[c * 10 + k] = ev[k] * inv;
        // slot 8: candidate (p-chain only), else zero pad
        if (sign == 0 && (c == li || c == lj)) {
            sr[c * 10 + 8] = (c == li) ? lj : li;
            sv[c * 10 + 8] = v2.x * inv;
        } else {
            sr[c * 10 + 8] = 0;
            sv[c * 10 + 8] = 0.f;
        }
    }
    for (int i = tid; i < 4096; i += CT)
        *(float4*)(A + i * 4) = make_float4(0.f, 0.f, 0.f, 0.f);
    __syncthreads();

    // T2 via sparse x sparse scatter (thread per row; zero-padded slots add 0)
    if (tid < 128) {
        int c = tid;
        #pragma unroll
        for (int k = 0; k < 9; ++k) {
            float v = sv[c * 10 + k];
            int r = sr[c * 10 + k];
            #pragma unroll
            for (int j = 0; j < 9; ++j)
                A[c * 128 + sr[r * 10 + j]] += v * sv[r * 10 + j];
        }
    }
    __syncthreads();

    // t2 + k=2 entries (from T2 in A)
    block_sum16((tid < 128) ? A[tid * 129] : 0.f, red, &res[0], tid);
    if (tid == 0) {
        res[7]  = A[li * 129] + A[lj * 129];
        res[14] = A[li * 128 + lj] + A[lj * 128 + li];
    }

    spstep(A, Bm, sv, sr, warp, lane);   // T3 = T * T2
    __syncthreads();

    block_sum16((tid < 128) ? Bm[tid * 129] : 0.f, red, &res[1], tid);  // t3
    if (tid == 0) {
        res[8]  = Bm[li * 129] + Bm[lj * 129];
        res[15] = Bm[li * 128 + lj] + Bm[lj * 128 + li];
    }
    __syncthreads();                            // all T2 reads done

    spstep(Bm, A, sv, sr, warp, lane);   // T4 = T * T3 (overwrites T2)
    __syncthreads();

    block_sum16((tid < 128) ? A[tid * 129] : 0.f, red, &res[2], tid);   // t4
    if (tid == 0) {
        res[9]  = A[li * 129] + A[lj * 129];
        res[16] = A[li * 128 + lj] + A[lj * 128 + li];
    }

    // t5 = tr(T * T4) via sparse rep
    {
        float s5 = 0.f;
        if (tid < 128) {
            #pragma unroll
            for (int k = 0; k < 9; ++k)
                s5 = fmaf(sv[tid * 10 + k], A[sr[tid * 10 + k] * 128 + tid], s5);
        }
        block_sum16(s5, red, &res[3], tid);
    }

    // t6 = <T3,T3^T>, t7 = <T3,T4^T>, t8 = <T4,T4^T> — diagonal walk, conflict-free
    {
        float t6 = 0.f, t7 = 0.f, t8 = 0.f;
        #pragma unroll 4
        for (int s = 0; s < 32; ++s) {
            int g = s * CT + tid;
            int a = g & 127, d = g >> 7;
            int b2 = (a + d) & 127;
            float x3ab = Bm[a * 128 + b2], x3ba = Bm[b2 * 128 + a];
            float x4ab = A[a * 128 + b2],  x4ba = A[b2 * 128 + a];
            t6 = fmaf(x3ab, x3ba, t6);
            t7 = fmaf(x3ab, x4ba, t7);
            t8 = fmaf(x4ab, x4ba, t8);
        }
        block_sum3(t6, t7, t8, red, &res[4], &res[5], &res[6], tid);
    }

    // k=5 entries: T5[u,v] = sum_k val_k(u) * T4[rws_k(u), v]
    if (tid == 0) {
        float eii = 0.f, eij = 0.f, eji = 0.f, ejj = 0.f;
        #pragma unroll
        for (int k = 0; k < 9; ++k) {
            float v = sv[li * 10 + k]; int r = sr[li * 10 + k];
            eii = fmaf(v, A[r * 128 + li], eii);
            eij = fmaf(v, A[r * 128 + lj], eij);
        }
        #pragma unroll
        for (int k = 0; k < 9; ++k) {
            float v = sv[lj * 10 + k]; int r = sr[lj * 10 + k];
            eji = fmaf(v, A[r * 128 + li], eji);
            ejj = fmaf(v, A[r * 128 + lj], ejj);
        }
        res[10] = eii + ejj;   // nl5
        res[17] = eij + eji;   // ll5
    }

    // extract columns li/lj of T3 and T4
    {
        int w = tid >> 7, m = tid & 127;
        const float* M = (w < 2) ? Bm : A;
        int v = (w & 1) ? lj : li;
        colb[w * 128 + m] = M[m * 128 + v];
    }
    __syncthreads();

    // 12 row.col dots for k = 6,7,8 entries
    if (warp < 12) {
        const float* R; int u; const float* C;
        if (warp < 4)      { R = Bm; u = (warp < 2) ? li : lj; C = colb + (warp & 1) * 128; }
        else if (warp < 8) { R = Bm; u = (warp < 6) ? li : lj; C = colb + (2 + (warp & 1)) * 128; }
        else               { R = A;  u = (warp < 10) ? li : lj; C = colb + (2 + (warp & 1)) * 128; }
        float s = 0.f;
        #pragma unroll
        for (int q = 0; q < 4; ++q) { int m = lane + 32 * q; s = fmaf(R[u * 128 + m], C[m], s); }
        #pragma unroll
        for (int off = 16; off; off >>= 1) s += __shfl_down_sync(0xffffffffu, s, off);
        if (lane == 0) ebuf[warp] = s;
    }
    __syncthreads();
    if (tid == 0) {
        res[11] = ebuf[0] + ebuf[3];   res[18] = ebuf[1] + ebuf[2];    // nl6, ll6
        res[12] = ebuf[4] + ebuf[7];   res[19] = ebuf[5] + ebuf[6];    // nl7, ll7
        res[13] = ebuf[8] + ebuf[11];  res[20] = ebuf[9] + ebuf[10];   // nl8, ll8
    }
    __syncthreads();
    if (tid < 21) g_feats[(size_t)bid * 21 + tid] = res[tid];
}

// ============================================================================
// Kernel 3: feature assembly + MLP
// ============================================================================
__global__ void mlp_kernel(const float* __restrict__ W1, const float* __restrict__ b1,
                           const float* __restrict__ W2, const float* __restrict__ b2,
                           float* __restrict__ out) {
    const int b = blockIdx.x;
    const int t = threadIdx.x;
    __shared__ float feat[72];

    for (int s = t; s < 72; s += 32) {
        float v;
        if (s < 14) {                       // gl = trace_p - trace_m
            int h = s / 7, k = s % 7;
            v = g_feats[((size_t)(h * 256 + b)) * 21 + k]
              - g_feats[((size_t)((2 + h) * 256 + b)) * 21 + k];
        } else if (s < 16) {                // omega
            v = g_omega[b * 2 + (s - 14)];
        } else {
            int m = (s - 16) % 14;
            int blk = (s - 16) / 14;        // 0 nlp, 1 nlm, 2 llp, 3 llm
            int h = m / 7, k = m % 7;
            int sgn = blk & 1;
            int off = (blk < 2) ? 7 : 14;
            v = g_feats[((size_t)((sgn * 2 + h) * 256 + b)) * 21 + off + k];
        }
        feat[s] = v;
    }
    __syncwarp();

    float h1 = b1[t];
    #pragma unroll 8
    for (int m = 0; m < 72; ++m) h1 = fmaf(feat[m], W1[m * 32 + t], h1);
    h1 = fmaxf(h1, 0.f);
    float v = h1 * W2[t];
    #pragma unroll
    for (int off = 16; off; off >>= 1) v += __shfl_down_sync(0xffffffffu, v, off);
    if (t == 0) out[b] = v + b2[0];
}

// ============================================================================
extern "C" void kernel_launch(void* const* d_in, const int* in_sizes, int n_in,
                              void* d_out, int out_size) {
    (void)in_sizes; (void)n_in; (void)out_size;
    const float* z_table = (const float*)d_in[0];
    const float* conv_W  = (const float*)d_in[1];
    const float* conv_b  = (const float*)d_in[2];
    const float* k1_W    = (const float*)d_in[3];
    const float* k1_b    = (const float*)d_in[4];
    const float* q1_W    = (const float*)d_in[5];
    const float* q1_b    = (const float*)d_in[6];
    const float* k2_W    = (const float*)d_in[7];
    const float* k2_b    = (const float*)d_in[8];
    const float* q2_W    = (const float*)d_in[9];
    const float* q2_b    = (const float*)d_in[10];
    const float* mlp_W1  = (const float*)d_in[11];
    const float* mlp_b1  = (const float*)d_in[12];
    const float* mlp_W2  = (const float*)d_in[13];
    const float* mlp_b2  = (const float*)d_in[14];
    const int*   z        = (const int*)d_in[15];
    const int*   edge_row = (const int*)d_in[16];
    const int*   node_i   = (const int*)d_in[20];
    const int*   node_j   = (const int*)d_in[21];
    float* out = (float*)d_out;

    cudaFuncSetAttribute(batch_kernel, cudaFuncAttributeMaxDynamicSharedMemorySize, SMB_FLOATS * 4);
    cudaFuncSetAttribute(chain_kernel, cudaFuncAttributeMaxDynamicSharedMemorySize, SMC_FLOATS * 4);

    batch_kernel<<<NB, 256, SMB_FLOATS * 4>>>(
        z_table, conv_W, conv_b, k1_W, k1_b, q1_W, q1_b,
        k2_W, k2_b, q2_W, q2_b, z, edge_row, node_i, node_j);
    chain_kernel<<<4 * NB, CT, SMC_FLOATS * 4>>>(node_i, node_j);
    mlp_kernel<<<NB, 32>>>(mlp_W1, mlp_b1, mlp_W2, mlp_b2, out);
}

// round 5
// speedup vs baseline: 3.0956x; 1.0105x over previous
#include <cuda_runtime.h>
#include <math.h>

#define NB 256

// Compact global scratch (static; no runtime allocation)
__device__ float g_vals[(size_t)2 * 256 * 128 * 12];  // [h][b][c]{ews0..7, ec, invp, invm, pad}
__device__ uint2 g_rows[256 * 128];                   // [b][c] 8 packed row bytes
__device__ float g_feats[4 * NB * 21];                // per chain: t2..8, nl2..8, ll2..8
__device__ float g_omega[NB * 2];

// ============================================================================
// Kernel 1: per-batch GCN (sparse agg) + attention -> compact softmax rep
// smem floats: X 0(4224,str33) XW 4224(4224,str33) Q2 8448(8320,str65)
//   K2 16768(8320,str65) dinv 25088(128) wcs 25216(4) zloc 25220(128i) rows 25348(1024i)
// ============================================================================
#define SMB_FLOATS 26372

// In (stride 33) @ W(32x32, gmem) -> Out (stride 33). act: 0 none, 1 leaky(+bias)
__device__ __forceinline__ void gemm32(const float* __restrict__ In,
                                       const float* __restrict__ Wg,
                                       const float* __restrict__ bias,
                                       float* __restrict__ Out, int tid, int act) {
    const int r = tid >> 1;
    const int fh = (tid & 1) * 16;
    float acc[16];
    #pragma unroll
    for (int u = 0; u < 16; ++u) acc[u] = 0.f;
    #pragma unroll
    for (int m = 0; m < 32; ++m) {
        float a = In[r * 33 + m];
        float4 w0 = __ldg((const float4*)(Wg + m * 32 + fh));
        float4 w1 = __ldg((const float4*)(Wg + m * 32 + fh + 4));
        float4 w2 = __ldg((const float4*)(Wg + m * 32 + fh + 8));
        float4 w3 = __ldg((const float4*)(Wg + m * 32 + fh + 12));
        acc[0]  = fmaf(a, w0.x, acc[0]);  acc[1]  = fmaf(a, w0.y, acc[1]);
        acc[2]  = fmaf(a, w0.z, acc[2]);  acc[3]  = fmaf(a, w0.w, acc[3]);
        acc[4]  = fmaf(a, w1.x, acc[4]);  acc[5]  = fmaf(a, w1.y, acc[5]);
        acc[6]  = fmaf(a, w1.z, acc[6]);  acc[7]  = fmaf(a, w1.w, acc[7]);
        acc[8]  = fmaf(a, w2.x, acc[8]);  acc[9]  = fmaf(a, w2.y, acc[9]);
        acc[10] = fmaf(a, w2.z, acc[10]); acc[11] = fmaf(a, w2.w, acc[11]);
        acc[12] = fmaf(a, w3.x, acc[12]); acc[13] = fmaf(a, w3.y, acc[13]);
        acc[14] = fmaf(a, w3.z, acc[14]); acc[15] = fmaf(a, w3.w, acc[15]);
    }
    #pragma unroll
    for (int u = 0; u < 16; ++u) {
        float s = acc[u];
        if (act) {
            s += __ldg(bias + fh + u);
            s = (s > 0.f) ? s : 0.2f * s;
        }
        Out[r * 33 + fh + u] = s;
    }
}

// In (stride 33) @ W(32x64, gmem) + bias -> Out (stride 65)
__device__ __forceinline__ void gemm64(const float* __restrict__ In,
                                       const float* __restrict__ Wg,
                                       const float* __restrict__ bias,
                                       float* __restrict__ Out, int tid) {
    const int r = tid & 127;
    const int fh = (tid >> 7) * 32;
    float acc[32];
    #pragma unroll
    for (int u = 0; u < 32; ++u) acc[u] = 0.f;
    #pragma unroll
    for (int m = 0; m < 32; ++m) {
        float a = In[r * 33 + m];
        #pragma unroll
        for (int q = 0; q < 8; ++q) {
            float4 w = __ldg((const float4*)(Wg + m * 64 + fh + 4 * q));
            acc[4*q]   = fmaf(a, w.x, acc[4*q]);
            acc[4*q+1] = fmaf(a, w.y, acc[4*q+1]);
            acc[4*q+2] = fmaf(a, w.z, acc[4*q+2]);
            acc[4*q+3] = fmaf(a, w.w, acc[4*q+3]);
        }
    }
    #pragma unroll
    for (int u = 0; u < 32; ++u)
        Out[r * 65 + fh + u] = acc[u] + __ldg(bias + fh + u);
}

__global__ __launch_bounds__(256, 2) void batch_kernel(
    const float* __restrict__ z_table, const float* __restrict__ conv_W, const float* __restrict__ conv_b,
    const float* __restrict__ k1_W, const float* __restrict__ k1_b,
    const float* __restrict__ q1_W, const float* __restrict__ q1_b,
    const float* __restrict__ k2_W, const float* __restrict__ k2_b,
    const float* __restrict__ q2_W, const float* __restrict__ q2_b,
    const int* __restrict__ z, const int* __restrict__ edge_row,
    const int* __restrict__ node_i, const int* __restrict__ node_j)
{
    extern __shared__ float sm[];
    float* X    = sm;            // stride 33
    float* XW   = sm + 4224;     // stride 33
    float* Q2   = sm + 8448;     // stride 65
    float* K2   = sm + 16768;    // stride 65
    float* dinv = sm + 25088;
    float* wcs  = sm + 25216;
    int*   zloc = (int*)(sm + 25220);
    int*   rows = (int*)(sm + 25348);  // [c][k]

    const int tid   = threadIdx.x;
    const int b     = blockIdx.x;
    const int gbase = b * 128;
    const int ebase = b * 1024;
    const int li    = node_i[b] - gbase;
    const int lj    = node_j[b] - gbase;

    if (tid < 128) {
        float dg = 9.f + (tid == li ? 1.f : 0.f) + (tid == lj ? 1.f : 0.f);
        dinv[tid] = rsqrtf(dg);
        zloc[tid] = z[gbase + tid];
    }
    for (int e = tid; e < 1024; e += 256)
        rows[(e & 127) * 8 + (e >> 7)] = edge_row[ebase + e] - gbase;
    __syncthreads();

    for (int i = tid; i < 4096; i += 256)
        X[(i >> 5) * 33 + (i & 31)] = z_table[zloc[i >> 5] * 32 + (i & 31)];
    __syncthreads();

    const int warp = tid >> 5, lane = tid & 31;

    // 3 GCN layers: X <- act( sparse-agg( X @ W_l ) + b_l )
    for (int l = 0; l < 3; ++l) {
        gemm32(X, conv_W + l * 1024, nullptr, XW, tid, 0);
        __syncthreads();
        for (int it = 0; it < 16; ++it) {
            int c = it * 8 + warp;
            float dc = dinv[c];
            float acc = __ldg(conv_b + l * 32 + lane) + dc * dc * XW[c * 33 + lane];
            #pragma unroll
            for (int k = 0; k < 8; ++k) {
                int r = rows[c * 8 + k];
                acc = fmaf(dinv[r] * dc, XW[r * 33 + lane], acc);
            }
            if (c == li)      acc = fmaf(dinv[lj] * dc, XW[lj * 33 + lane], acc);
            else if (c == lj) acc = fmaf(dinv[li] * dc, XW[li * 33 + lane], acc);
            X[c * 33 + lane] = (l < 2) ? fmaxf(acc, 0.f) : acc;
        }
        __syncthreads();
    }

    // Q path: Q2 = (leaky(X@k1_W+k1_b)) @ k2_W + k2_b   (used at edge ROWS)
    gemm32(X, k1_W, k1_b, XW, tid, 1);
    __syncthreads();
    gemm64(XW, k2_W, k2_b, Q2, tid);
    __syncthreads();
    // K path (no dependence between XW uses thanks to syncs)
    gemm32(X, q1_W, q1_b, XW, tid, 1);
    __syncthreads();
    gemm64(XW, q2_W, q2_b, K2, tid);
    __syncthreads();

    // Attention per (col c, head h): logits + segment softmax -> compact rep
    const int c = tid & 127;
    const int h = tid >> 7;
    const float isq = 0.17677669529663687f;  // 1/sqrt(32)

    float kv[32];
    #pragma unroll
    for (int f = 0; f < 32; ++f) kv[f] = K2[c * 65 + h * 32 + f];

    float w[8];
    int rws[8];
    #pragma unroll
    for (int k = 0; k < 8; ++k) {
        int r = rows[c * 8 + k];
        rws[k] = r;
        float s = 0.f;
        #pragma unroll 8
        for (int f = 0; f < 32; ++f) s = fmaf(Q2[r * 65 + h * 32 + f], kv[f], s);
        w[k] = s * isq;
    }
    bool cand = (c == li) || (c == lj);
    float w8 = 0.f;
    if (cand) {
        int r = (c == li) ? lj : li;
        float s = 0.f;
        #pragma unroll 8
        for (int f = 0; f < 32; ++f) s = fmaf(Q2[r * 65 + h * 32 + f], kv[f], s);
        w8 = s * isq;
        wcs[h * 2 + (c == li ? 1 : 0)] = 1.f / (1.f + expf(-w8));
    }
    float wmax = w[0];
    #pragma unroll
    for (int k = 1; k < 8; ++k) wmax = fmaxf(wmax, w[k]);
    if (cand) wmax = fmaxf(wmax, w8);

    float ews[8];
    float sum8 = 0.f;
    #pragma unroll
    for (int k = 0; k < 8; ++k) { ews[k] = expf(w[k] - wmax); sum8 += ews[k]; }
    float ec = cand ? expf(w8 - wmax) : 0.f;
    float invp = 1.f / (sum8 + ec + 1e-16f);
    float invm = 1.f / (sum8 + 1e-16f);

    size_t vb = (((size_t)h * 256 + b) * 128 + c) * 12;
    *(float4*)(g_vals + vb)     = make_float4(ews[0], ews[1], ews[2], ews[3]);
    *(float4*)(g_vals + vb + 4) = make_float4(ews[4], ews[5], ews[6], ews[7]);
    *(float4*)(g_vals + vb + 8) = make_float4(ec, invp, invm, 0.f);
    if (h == 0) {
        uint2 pk;
        pk.x = (unsigned)rws[0] | ((unsigned)rws[1] << 8) | ((unsigned)rws[2] << 16) | ((unsigned)rws[3] << 24);
        pk.y = (unsigned)rws[4] | ((unsigned)rws[5] << 8) | ((unsigned)rws[6] << 16) | ((unsigned)rws[7] << 24);
        g_rows[b * 128 + c] = pk;
    }
    __syncthreads();
    if (tid < 2) g_omega[b * 2 + tid] = wcs[tid * 2] + wcs[tid * 2 + 1];
}

// ============================================================================
// Kernel 2: per-chain sparse matrix powers + feature extraction  (CT = 1024)
// chain id: sign = bid>>9 (0=p,1=m), h = (bid>>8)&1, b = bid&255
// smem floats: A 0(16384) Bm 16384(16384) sv 32768(1280) sr 34048(1280i)
//   colb 35328(512) res 35840(32) red 35872(96) ebuf 35968(16)
// ============================================================================
#define CT 1024
#define SMC_FLOATS 35984

__device__ __forceinline__ void bsum(float v, float* red, float* slot, int tid) {
    #pragma unroll
    for (int off = 16; off; off >>= 1) v += __shfl_down_sync(0xffffffffu, v, off);
    if ((tid & 31) == 0) red[tid >> 5] = v;
    __syncthreads();
    if (tid < 32) {
        float s = red[tid];
        #pragma unroll
        for (int off = 16; off; off >>= 1) s += __shfl_down_sync(0xffffffffu, s, off);
        if (tid == 0) *slot = s;
    }
    __syncthreads();
}

__device__ __forceinline__ void bsum3(float v0, float v1, float v2, float* red,
                                      float* s0, float* s1, float* s2, int tid) {
    #pragma unroll
    for (int off = 16; off; off >>= 1) {
        v0 += __shfl_down_sync(0xffffffffu, v0, off);
        v1 += __shfl_down_sync(0xffffffffu, v1, off);
        v2 += __shfl_down_sync(0xffffffffu, v2, off);
    }
    if ((tid & 31) == 0) {
        red[tid >> 5] = v0; red[32 + (tid >> 5)] = v1; red[64 + (tid >> 5)] = v2;
    }
    __syncthreads();
    if (tid < 32) {
        float a = red[tid], b = red[32 + tid], c = red[64 + tid];
        #pragma unroll
        for (int off = 16; off; off >>= 1) {
            a += __shfl_down_sync(0xffffffffu, a, off);
            b += __shfl_down_sync(0xffffffffu, b, off);
            c += __shfl_down_sync(0xffffffffu, c, off);
        }
        if (tid == 0) { *s0 = a; *s1 = b; *s2 = c; }
    }
    __syncthreads();
}

// Out = T(sparse, fixed 9) * In : row c of Out = sum_k v_k(c) * row r_k(c) of In
__device__ __forceinline__ void spstep(const float* __restrict__ In, float* __restrict__ Out,
                                       const float* __restrict__ sv, const int* __restrict__ sr,
                                       int warp, int lane) {
    const float4* In4 = (const float4*)In;
    #pragma unroll
    for (int it = 0; it < 4; ++it) {
        int c = it * 32 + warp;
        float v[9]; int r[9];
        #pragma unroll
        for (int k = 0; k < 9; ++k) { v[k] = sv[c * 10 + k]; r[k] = sr[c * 10 + k]; }
        float4 acc = make_float4(0.f, 0.f, 0.f, 0.f);
        #pragma unroll
        for (int k = 0; k < 9; ++k) {
            float4 x = In4[r[k] * 32 + lane];
            acc.x = fmaf(v[k], x.x, acc.x);
            acc.y = fmaf(v[k], x.y, acc.y);
            acc.z = fmaf(v[k], x.z, acc.z);
            acc.w = fmaf(v[k], x.w, acc.w);
        }
        *(float4*)(Out + c * 128 + lane * 4) = acc;
    }
}

__global__ __launch_bounds__(CT) void chain_kernel(const int* __restrict__ node_i,
                                                   const int* __restrict__ node_j) {
    extern __shared__ float sm[];
    float* A    = sm;            // T2, later T4
    float* Bm   = sm + 16384;    // scatter half, then T3
    float* sv   = sm + 32768;    // [128][10]
    int*   sr   = (int*)(sm + 34048);
    float* colb = sm + 35328;    // 4 x 128
    float* res  = sm + 35840;    // 32
    float* red  = sm + 35872;    // 96
    float* ebuf = sm + 35968;    // 16

    const int tid  = threadIdx.x;
    const int bid  = blockIdx.x;
    const int sign = bid >> 9;
    const int h    = (bid >> 8) & 1;
    const int b    = bid & 255;
    const int li   = node_i[b] - b * 128;
    const int lj   = node_j[b] - b * 128;
    const int warp = tid >> 5, lane = tid & 31;

    // Build sparse rep (fixed 9 slots; pad v=0,r=0)
    if (tid < 128) {
        int c = tid;
        uint2 pr = g_rows[b * 128 + c];
        const float4* gv = (const float4*)(g_vals + (((size_t)h * 256 + b) * 128 + c) * 12);
        float4 v0 = gv[0], v1 = gv[1], v2 = gv[2];
        float inv = (sign == 0) ? v2.y : v2.z;
        float ev[8] = {v0.x, v0.y, v0.z, v0.w, v1.x, v1.y, v1.z, v1.w};
        #pragma unroll
        for (int k = 0; k < 4; ++k) {
            sr[c * 10 + k]     = (pr.x >> (8 * k)) & 255;
            sr[c * 10 + 4 + k] = (pr.y >> (8 * k)) & 255;
        }
        #pragma unroll
        for (int k = 0; k < 8; ++k) sv[c * 10 + k] = ev[k] * inv;
        if (sign == 0 && (c == li || c == lj)) {
            sr[c * 10 + 8] = (c == li) ? lj : li;
            sv[c * 10 + 8] = v2.x * inv;
        } else {
            sr[c * 10 + 8] = 0;
            sv[c * 10 + 8] = 0.f;
        }
    }
    // zero both scatter buffers
    for (int i = tid; i < 8192; i += CT)
        *(float4*)(sm + i * 4) = make_float4(0.f, 0.f, 0.f, 0.f);
    __syncthreads();

    // T2 via sparse x sparse scatter, split across two threads/row into A and Bm
    if (tid < 256) {
        int c = tid >> 1;
        float* dst = (tid & 1) ? (Bm + c * 128) : (A + c * 128);
        int k0 = (tid & 1) ? 4 : 0;
        int kend = (tid & 1) ? 9 : 4;
        for (int k = k0; k < kend; ++k) {
            float v = sv[c * 10 + k];
            int r = sr[c * 10 + k];
            #pragma unroll
            for (int j = 0; j < 9; ++j)
                dst[sr[r * 10 + j]] += v * sv[r * 10 + j];
        }
    }
    __syncthreads();
    // merge: A += Bm  (T2 in A)
    for (int i = tid; i < 4096; i += CT) {
        float4 a4 = *(const float4*)(A + i * 4);
        float4 b4 = *(const float4*)(Bm + i * 4);
        a4.x += b4.x; a4.y += b4.y; a4.z += b4.z; a4.w += b4.w;
        *(float4*)(A + i * 4) = a4;
    }
    __syncthreads();

    // t2 + k=2 entries
    if (tid == 0) {
        res[7]  = A[li * 129] + A[lj * 129];
        res[14] = A[li * 128 + lj] + A[lj * 128 + li];
    }
    bsum((tid < 128) ? A[tid * 129] : 0.f, red, &res[0], tid);

    spstep(A, Bm, sv, sr, warp, lane);   // T3 = T * T2
    __syncthreads();

    if (tid == 0) {
        res[8]  = Bm[li * 129] + Bm[lj * 129];
        res[15] = Bm[li * 128 + lj] + Bm[lj * 128 + li];
    }
    bsum((tid < 128) ? Bm[tid * 129] : 0.f, red, &res[1], tid);  // t3

    spstep(Bm, A, sv, sr, warp, lane);   // T4 = T * T3 (overwrites T2)
    __syncthreads();

    if (tid == 0) {
        res[9]  = A[li * 129] + A[lj * 129];
        res[16] = A[li * 128 + lj] + A[lj * 128 + li];
    }
    bsum((tid < 128) ? A[tid * 129] : 0.f, red, &res[2], tid);   // t4

    // t5 = tr(T * T4) via sparse rep
    {
        float s5 = 0.f;
        if (tid < 128) {
            #pragma unroll
            for (int k = 0; k < 9; ++k)
                s5 = fmaf(sv[tid * 10 + k], A[sr[tid * 10 + k] * 128 + tid], s5);
        }
        bsum(s5, red, &res[3], tid);
    }

    // t6 = <T3,T3^T>, t7 = <T3,T4^T>, t8 = <T4,T4^T> — unordered-pair walk
    {
        float t6 = 0.f, t7 = 0.f, t8 = 0.f;
        // strips d = 1..63: each unordered pair once, weight 2 (sym)
        for (int g = tid; g < 8064; g += CT) {
            int d = (g >> 7) + 1;
            int a = g & 127;
            int y = (a + d) & 127;
            float x3ab = Bm[a * 128 + y], x3ba = Bm[y * 128 + a];
            float x4ab = A[a * 128 + y],  x4ba = A[y * 128 + a];
            t6 = fmaf(2.f * x3ab, x3ba, t6);
            t7 = fmaf(x3ab, x4ba, fmaf(x3ba, x4ab, t7));
            t8 = fmaf(2.f * x4ab, x4ba, t8);
        }
        // d = 64 strip (pairs counted once over a<64)
        if (tid < 64) {
            int a = tid, y = a + 64;
            float x3ab = Bm[a * 128 + y], x3ba = Bm[y * 128 + a];
            float x4ab = A[a * 128 + y],  x4ba = A[y * 128 + a];
            t6 = fmaf(2.f * x3ab, x3ba, t6);
            t7 = fmaf(x3ab, x4ba, fmaf(x3ba, x4ab, t7));
            t8 = fmaf(2.f * x4ab, x4ba, t8);
        }
        // diagonal
        if (tid < 128) {
            float d3 = Bm[tid * 129], d4 = A[tid * 129];
            t6 = fmaf(d3, d3, t6);
            t7 = fmaf(d3, d4, t7);
            t8 = fmaf(d4, d4, t8);
        }
        bsum3(t6, t7, t8, red, &res[4], &res[5], &res[6], tid);
    }

    // k=5 entries (4 threads) + column extraction (512 threads), same phase
    if (tid < 4) {
        int u = (tid < 2) ? li : lj;
        int v = (tid & 1) ? lj : li;
        float s = 0.f;
        #pragma unroll
        for (int k = 0; k < 9; ++k)
            s = fmaf(sv[u * 10 + k], A[sr[u * 10 + k] * 128 + v], s);
        ebuf[12 + tid] = s;   // order: ii, ij, ji, jj
    }
    if (tid >= 512 && tid < 1024) {
        int t = tid - 512;
        int w = t >> 7, m = t & 127;
        const float* M = (w < 2) ? Bm : A;   // T3 cols, T4 cols
        int v = (w & 1) ? lj : li;
        colb[w * 128 + m] = M[m * 128 + v];
    }
    __syncthreads();

    // 12 row.col dots for k = 6,7,8 entries
    if (warp < 12) {
        const float* R; int u; const float* C;
        if (warp < 4)      { R = Bm; u = (warp < 2) ? li : lj; C = colb + (warp & 1) * 128; }
        else if (warp < 8) { R = Bm; u = (warp < 6) ? li : lj; C = colb + (2 + (warp & 1)) * 128; }
        else               { R = A;  u = (warp < 10) ? li : lj; C = colb + (2 + (warp & 1)) * 128; }
        float s = 0.f;
        #pragma unroll
        for (int q = 0; q < 4; ++q) { int m = lane + 32 * q; s = fmaf(R[u * 128 + m], C[m], s); }
        #pragma unroll
        for (int off = 16; off; off >>= 1) s += __shfl_down_sync(0xffffffffu, s, off);
        if (lane == 0) ebuf[warp] = s;
    }
    __syncthreads();
    if (tid == 0) {
        res[10] = ebuf[12] + ebuf[15];  res[17] = ebuf[13] + ebuf[14];  // nl5, ll5
        res[11] = ebuf[0] + ebuf[3];    res[18] = ebuf[1] + ebuf[2];    // nl6, ll6
        res[12] = ebuf[4] + ebuf[7];    res[19] = ebuf[5] + ebuf[6];    // nl7, ll7
        res[13] = ebuf[8] + ebuf[11];   res[20] = ebuf[9] + ebuf[10];   // nl8, ll8
    }
    __syncthreads();
    if (tid < 21) g_feats[(size_t)bid * 21 + tid] = res[tid];
}

// ============================================================================
// Kernel 3: feature assembly + MLP
// ============================================================================
__global__ void mlp_kernel(const float* __restrict__ W1, const float* __restrict__ b1,
                           const float* __restrict__ W2, const float* __restrict__ b2,
                           float* __restrict__ out) {
    const int b = blockIdx.x;
    const int t = threadIdx.x;
    __shared__ float feat[72];

    for (int s = t; s < 72; s += 32) {
        float v;
        if (s < 14) {                       // gl = trace_p - trace_m
            int h = s / 7, k = s % 7;
            v = g_feats[((size_t)(h * 256 + b)) * 21 + k]
              - g_feats[((size_t)((2 + h) * 256 + b)) * 21 + k];
        } else if (s < 16) {                // omega
            v = g_omega[b * 2 + (s - 14)];
        } else {
            int m = (s - 16) % 14;
            int blk = (s - 16) / 14;        // 0 nlp, 1 nlm, 2 llp, 3 llm
            int h = m / 7, k = m % 7;
            int sgn = blk & 1;
            int off = (blk < 2) ? 7 : 14;
            v = g_feats[((size_t)((sgn * 2 + h) * 256 + b)) * 21 + off + k];
        }
        feat[s] = v;
    }
    __syncwarp();

    float h1 = b1[t];
    #pragma unroll 8
    for (int m = 0; m < 72; ++m) h1 = fmaf(feat[m], W1[m * 32 + t], h1);
    h1 = fmaxf(h1, 0.f);
    float v = h1 * W2[t];
    #pragma unroll
    for (int off = 16; off; off >>= 1) v += __shfl_down_sync(0xffffffffu, v, off);
    if (t == 0) out[b] = v + b2[0];
}

// ============================================================================
extern "C" void kernel_launch(void* const* d_in, const int* in_sizes, int n_in,
                              void* d_out, int out_size) {
    (void)in_sizes; (void)n_in; (void)out_size;
    const float* z_table = (const float*)d_in[0];
    const float* conv_W  = (const float*)d_in[1];
    const float* conv_b  = (const float*)d_in[2];
    const float* k1_W    = (const float*)d_in[3];
    const float* k1_b    = (const float*)d_in[4];
    const float* q1_W    = (const float*)d_in[5];
    const float* q1_b    = (const float*)d_in[6];
    const float* k2_W    = (const float*)d_in[7];
    const float* k2_b    = (const float*)d_in[8];
    const float* q2_W    = (const float*)d_in[9];
    const float* q2_b    = (const float*)d_in[10];
    const float* mlp_W1  = (const float*)d_in[11];
    const float* mlp_b1  = (const float*)d_in[12];
    const float* mlp_W2  = (const float*)d_in[13];
    const float* mlp_b2  = (const float*)d_in[14];
    const int*   z        = (const int*)d_in[15];
    const int*   edge_row = (const int*)d_in[16];
    const int*   node_i   = (const int*)d_in[20];
    const int*   node_j   = (const int*)d_in[21];
    float* out = (float*)d_out;

    cudaFuncSetAttribute(batch_kernel, cudaFuncAttributeMaxDynamicSharedMemorySize, SMB_FLOATS * 4);
    cudaFuncSetAttribute(chain_kernel, cudaFuncAttributeMaxDynamicSharedMemorySize, SMC_FLOATS * 4);

    batch_kernel<<<NB, 256, SMB_FLOATS * 4>>>(
        z_table, conv_W, conv_b, k1_W, k1_b, q1_W, q1_b,
        k2_W, k2_b, q2_W, q2_b, z, edge_row, node_i, node_j);
    chain_kernel<<<4 * NB, CT, SMC_FLOATS * 4>>>(node_i, node_j);
    mlp_kernel<<<NB, 32>>>(mlp_W1, mlp_b1, mlp_W2, mlp_b2, out);
}

// round 6
// speedup vs baseline: 3.3914x; 1.0956x over previous
#include <cuda_runtime.h>
#include <math.h>

#define NB 256

// Compact global scratch (static; no runtime allocation)
__device__ float g_vals[(size_t)2 * 256 * 128 * 12];  // [h][b][c]{ews0..7, ec, invp, invm, pad}
__device__ uint2 g_rows[256 * 128];                   // [b][c] 8 packed row bytes
__device__ float g_feats[4 * NB * 21];                // per chain: t2..8, nl2..8, ll2..8
__device__ float g_omega[NB * 2];

// ============================================================================
// Kernel 1: per-batch GCN + attention.
// smem floats: Wb 0(2048) X 2048(4224,str33) XW 6272(4224,str33)
//   Q2 10496(8320,str65) K2 18816(8320,str65) dinv 27136(128) wcs 27264(4)
//   rows8 27268(256 = 1024 uchar)   total 27524 floats = 110.1KB -> 2 CTA/SM
// ============================================================================
#define SMB_FLOATS 27524

__device__ __forceinline__ void copyW(const float* __restrict__ Wg, float* Wb,
                                      int n4, int tid) {
    const float4* s = (const float4*)Wg;
    float4* d = (float4*)Wb;
    for (int i = tid; i < n4; i += 256) d[i] = __ldg(s + i);
}

// In (stride 33) @ Wb(32x32 smem) -> Out (stride 33); act=1: +bias, leaky
__device__ __forceinline__ void gemm32(const float* __restrict__ In,
                                       const float* __restrict__ Wb,
                                       const float* __restrict__ bias,
                                       float* __restrict__ Out, int tid, int act) {
    const int tr = (tid >> 3) * 4;
    const int tc = tid & 7;
    float acc[4][4];
    #pragma unroll
    for (int i = 0; i < 4; ++i)
        #pragma unroll
        for (int u = 0; u < 4; ++u) acc[i][u] = 0.f;
    #pragma unroll
    for (int m = 0; m < 32; ++m) {
        float a0 = In[(tr + 0) * 33 + m], a1 = In[(tr + 1) * 33 + m];
        float a2 = In[(tr + 2) * 33 + m], a3 = In[(tr + 3) * 33 + m];
        #pragma unroll
        for (int u = 0; u < 4; ++u) {
            float w = Wb[m * 32 + tc + 8 * u];
            acc[0][u] = fmaf(a0, w, acc[0][u]);
            acc[1][u] = fmaf(a1, w, acc[1][u]);
            acc[2][u] = fmaf(a2, w, acc[2][u]);
            acc[3][u] = fmaf(a3, w, acc[3][u]);
        }
    }
    #pragma unroll
    for (int i = 0; i < 4; ++i)
        #pragma unroll
        for (int u = 0; u < 4; ++u) {
            float s = acc[i][u];
            if (act) {
                s += __ldg(bias + tc + 8 * u);
                s = (s > 0.f) ? s : 0.2f * s;
            }
            Out[(tr + i) * 33 + tc + 8 * u] = s;
        }
}

// In (stride 33) @ Wb(32x64 smem) + bias -> Out (stride 65)
__device__ __forceinline__ void gemm64(const float* __restrict__ In,
                                       const float* __restrict__ Wb,
                                       const float* __restrict__ bias,
                                       float* __restrict__ Out, int tid) {
    const int tr = (tid >> 3) * 4;
    const int tc = tid & 7;
    float acc[4][8];
    #pragma unroll
    for (int i = 0; i < 4; ++i)
        #pragma unroll
        for (int u = 0; u < 8; ++u) acc[i][u] = 0.f;
    #pragma unroll
    for (int m = 0; m < 32; ++m) {
        float a0 = In[(tr + 0) * 33 + m], a1 = In[(tr + 1) * 33 + m];
        float a2 = In[(tr + 2) * 33 + m], a3 = In[(tr + 3) * 33 + m];
        #pragma unroll
        for (int u = 0; u < 8; ++u) {
            float w = Wb[m * 64 + tc + 8 * u];
            acc[0][u] = fmaf(a0, w, acc[0][u]);
            acc[1][u] = fmaf(a1, w, acc[1][u]);
            acc[2][u] = fmaf(a2, w, acc[2][u]);
            acc[3][u] = fmaf(a3, w, acc[3][u]);
        }
    }
    #pragma unroll
    for (int i = 0; i < 4; ++i)
        #pragma unroll
        for (int u = 0; u < 8; ++u)
            Out[(tr + i) * 65 + tc + 8 * u] = acc[i][u] + __ldg(bias + tc + 8 * u);
}

__global__ __launch_bounds__(256, 2) void batch_kernel(
    const float* __restrict__ z_table, const float* __restrict__ conv_W, const float* __restrict__ conv_b,
    const float* __restrict__ k1_W, const float* __restrict__ k1_b,
    const float* __restrict__ q1_W, const float* __restrict__ q1_b,
    const float* __restrict__ k2_W, const float* __restrict__ k2_b,
    const float* __restrict__ q2_W, const float* __restrict__ q2_b,
    const int* __restrict__ z, const int* __restrict__ edge_row,
    const int* __restrict__ node_i, const int* __restrict__ node_j)
{
    extern __shared__ float sm[];
    float* Wb   = sm;            // 2048
    float* X    = sm + 2048;     // stride 33
    float* XW   = sm + 6272;     // stride 33
    float* Q2   = sm + 10496;    // stride 65
    float* K2   = sm + 18816;    // stride 65
    float* dinv = sm + 27136;
    float* wcs  = sm + 27264;
    unsigned char* rows8 = (unsigned char*)(sm + 27268);   // [c][k]

    const int tid   = threadIdx.x;
    const int b     = blockIdx.x;
    const int gbase = b * 128;
    const int ebase = b * 1024;
    const int li    = node_i[b] - gbase;
    const int lj    = node_j[b] - gbase;

    if (tid < 128) {
        float dg = 9.f + (tid == li ? 1.f : 0.f) + (tid == lj ? 1.f : 0.f);
        dinv[tid] = rsqrtf(dg);
    }
    for (int e = tid; e < 1024; e += 256)
        rows8[(e & 127) * 8 + (e >> 7)] = (unsigned char)(edge_row[ebase + e] - gbase);
    // embedding gather (z read per row via __ldg; L1-cached)
    for (int i = tid; i < 4096; i += 256) {
        int r = i >> 5, f = i & 31;
        X[r * 33 + f] = __ldg(z_table + __ldg(z + gbase + r) * 32 + f);
    }
    __syncthreads();

    const int warp = tid >> 5, lane = tid & 31;

    // 3 GCN layers: X <- act( sparse-agg( X @ W_l ) + b_l )
    for (int l = 0; l < 3; ++l) {
        copyW(conv_W + l * 1024, Wb, 256, tid);
        __syncthreads();
        gemm32(X, Wb, nullptr, XW, tid, 0);
        __syncthreads();
        for (int it = 0; it < 16; ++it) {
            int c = it * 8 + warp;
            float dc = dinv[c];
            float acc = __ldg(conv_b + l * 32 + lane) + dc * dc * XW[c * 33 + lane];
            #pragma unroll
            for (int k = 0; k < 8; ++k) {
                int r = rows8[c * 8 + k];
                acc = fmaf(dinv[r] * dc, XW[r * 33 + lane], acc);
            }
            if (c == li)      acc = fmaf(dinv[lj] * dc, XW[lj * 33 + lane], acc);
            else if (c == lj) acc = fmaf(dinv[li] * dc, XW[li * 33 + lane], acc);
            X[c * 33 + lane] = (l < 2) ? fmaxf(acc, 0.f) : acc;
        }
        __syncthreads();
    }

    // Q path: Q2 = (leaky(X@k1_W+k1_b)) @ k2_W + k2_b   (used at edge ROWS)
    copyW(k1_W, Wb, 256, tid);  __syncthreads();
    gemm32(X, Wb, k1_b, XW, tid, 1);  __syncthreads();
    copyW(k2_W, Wb, 512, tid);  __syncthreads();
    gemm64(XW, Wb, k2_b, Q2, tid);  __syncthreads();
    // K path
    copyW(q1_W, Wb, 256, tid);  __syncthreads();
    gemm32(X, Wb, q1_b, XW, tid, 1);  __syncthreads();
    copyW(q2_W, Wb, 512, tid);  __syncthreads();
    gemm64(XW, Wb, q2_b, K2, tid);  __syncthreads();

    // Attention per (col c, head h): logits + segment softmax -> compact rep
    const int c = tid & 127;
    const int h = tid >> 7;
    const float isq = 0.17677669529663687f;  // 1/sqrt(32)

    float kv[32];
    #pragma unroll
    for (int f = 0; f < 32; ++f) kv[f] = K2[c * 65 + h * 32 + f];

    float w[8];
    int rws[8];
    #pragma unroll
    for (int k = 0; k < 8; ++k) {
        int r = rows8[c * 8 + k];
        rws[k] = r;
        float s = 0.f;
        #pragma unroll 8
        for (int f = 0; f < 32; ++f) s = fmaf(Q2[r * 65 + h * 32 + f], kv[f], s);
        w[k] = s * isq;
    }
    bool cand = (c == li) || (c == lj);
    float w8 = 0.f;
    if (cand) {
        int r = (c == li) ? lj : li;
        float s = 0.f;
        #pragma unroll 8
        for (int f = 0; f < 32; ++f) s = fmaf(Q2[r * 65 + h * 32 + f], kv[f], s);
        w8 = s * isq;
        wcs[h * 2 + (c == li ? 1 : 0)] = 1.f / (1.f + expf(-w8));
    }
    float wmax = w[0];
    #pragma unroll
    for (int k = 1; k < 8; ++k) wmax = fmaxf(wmax, w[k]);
    if (cand) wmax = fmaxf(wmax, w8);

    float ews[8];
    float sum8 = 0.f;
    #pragma unroll
    for (int k = 0; k < 8; ++k) { ews[k] = expf(w[k] - wmax); sum8 += ews[k]; }
    float ec = cand ? expf(w8 - wmax) : 0.f;
    float invp = 1.f / (sum8 + ec + 1e-16f);
    float invm = 1.f / (sum8 + 1e-16f);

    size_t vb = (((size_t)h * 256 + b) * 128 + c) * 12;
    *(float4*)(g_vals + vb)     = make_float4(ews[0], ews[1], ews[2], ews[3]);
    *(float4*)(g_vals + vb + 4) = make_float4(ews[4], ews[5], ews[6], ews[7]);
    *(float4*)(g_vals + vb + 8) = make_float4(ec, invp, invm, 0.f);
    if (h == 0) {
        uint2 pk;
        pk.x = (unsigned)rws[0] | ((unsigned)rws[1] << 8) | ((unsigned)rws[2] << 16) | ((unsigned)rws[3] << 24);
        pk.y = (unsigned)rws[4] | ((unsigned)rws[5] << 8) | ((unsigned)rws[6] << 16) | ((unsigned)rws[7] << 24);
        g_rows[b * 128 + c] = pk;
    }
    __syncthreads();
    if (tid < 2) g_omega[b * 2 + tid] = wcs[tid * 2] + wcs[tid * 2 + 1];
}

// ============================================================================
// Kernel 2: per-chain sparse matrix powers + features.  CT=1024, 7 barriers.
// chain id: sign = bid>>9 (0=p,1=m), h = (bid>>8)&1, b = bid&255
// smem floats: A 0(16384) Bm 16384(16384) sv 32768(1280) sr 34048(1280i)
//   colb 35328(512) part 35840(224) res 36064(32) ebuf 36096(16)
// ============================================================================
#define CT 1024
#define SMC_FLOATS 36112

__device__ __forceinline__ float wred(float v) {
    #pragma unroll
    for (int off = 16; off; off >>= 1) v += __shfl_down_sync(0xffffffffu, v, off);
    return v;
}

// Out = T(sparse, fixed 9) * In
__device__ __forceinline__ void spstep(const float* __restrict__ In, float* __restrict__ Out,
                                       const float* __restrict__ sv, const int* __restrict__ sr,
                                       int warp, int lane) {
    const float4* In4 = (const float4*)In;
    #pragma unroll
    for (int it = 0; it < 4; ++it) {
        int c = it * 32 + warp;
        float v[9]; int r[9];
        #pragma unroll
        for (int k = 0; k < 9; ++k) { v[k] = sv[c * 10 + k]; r[k] = sr[c * 10 + k]; }
        float4 acc = make_float4(0.f, 0.f, 0.f, 0.f);
        #pragma unroll
        for (int k = 0; k < 9; ++k) {
            float4 x = In4[r[k] * 32 + lane];
            acc.x = fmaf(v[k], x.x, acc.x);
            acc.y = fmaf(v[k], x.y, acc.y);
            acc.z = fmaf(v[k], x.z, acc.z);
            acc.w = fmaf(v[k], x.w, acc.w);
        }
        *(float4*)(Out + c * 128 + lane * 4) = acc;
    }
}

__global__ __launch_bounds__(CT) void chain_kernel(const int* __restrict__ node_i,
                                                   const int* __restrict__ node_j) {
    extern __shared__ float sm[];
    float* A    = sm;            // T2, later T4
    float* Bm   = sm + 16384;    // T3
    float* sv   = sm + 32768;    // [128][10]
    int*   sr   = (int*)(sm + 34048);
    float* colb = sm + 35328;    // 4 x 128
    float* part = sm + 35840;    // [7][32] per-warp trace partials
    float* res  = sm + 36064;    // 32
    float* ebuf = sm + 36096;    // 16

    const int tid  = threadIdx.x;
    const int bid  = blockIdx.x;
    const int sign = bid >> 9;
    const int h    = (bid >> 8) & 1;
    const int b    = bid & 255;
    const int li   = node_i[b] - b * 128;
    const int lj   = node_j[b] - b * 128;
    const int warp = tid >> 5, lane = tid & 31;

    // Build sparse rep (fixed 9 slots; pad v=0,r=0) + zero A
    if (tid < 128) {
        int c = tid;
        uint2 pr = g_rows[b * 128 + c];
        const float4* gv = (const float4*)(g_vals + (((size_t)h * 256 + b) * 128 + c) * 12);
        float4 v0 = gv[0], v1 = gv[1], v2 = gv[2];
        float inv = (sign == 0) ? v2.y : v2.z;
        float ev[8] = {v0.x, v0.y, v0.z, v0.w, v1.x, v1.y, v1.z, v1.w};
        #pragma unroll
        for (int k = 0; k < 4; ++k) {
            sr[c * 10 + k]     = (pr.x >> (8 * k)) & 255;
            sr[c * 10 + 4 + k] = (pr.y >> (8 * k)) & 255;
        }
        #pragma unroll
        for (int k = 0; k < 8; ++k) sv[c * 10 + k] = ev[k] * inv;
        if (sign == 0 && (c == li || c == lj)) {
            sr[c * 10 + 8] = (c == li) ? lj : li;
            sv[c * 10 + 8] = v2.x * inv;
        } else {
            sr[c * 10 + 8] = 0;
            sv[c * 10 + 8] = 0.f;
        }
    }
    for (int i = tid; i < 4096; i += CT)
        *(float4*)(A + i * 4) = make_float4(0.f, 0.f, 0.f, 0.f);
    __syncthreads();                                              // (1)

    // T2 via sparse x sparse scatter (thread per row)
    if (tid < 128) {
        int c = tid;
        #pragma unroll
        for (int k = 0; k < 9; ++k) {
            float v = sv[c * 10 + k];
            int r = sr[c * 10 + k];
            #pragma unroll
            for (int j = 0; j < 9; ++j)
                A[c * 128 + sr[r * 10 + j]] += v * sv[r * 10 + j];
        }
    }
    __syncthreads();                                              // (2)

    // phase A: t2 partials + k2 entries; then T3 = T * T2
    {
        float p = (lane < 4) ? A[(4 * warp + lane) * 129] : 0.f;
        p = wred(p);
        if (lane == 0) part[warp] = p;                 // t2
        if (warp == 31 && lane == 0) {
            res[7]  = A[li * 129] + A[lj * 129];
            res[14] = A[li * 128 + lj] + A[lj * 128 + li];
        }
    }
    spstep(A, Bm, sv, sr, warp, lane);
    __syncthreads();                                              // (3)

    // phase B: t3 partials + k3 entries; then T4 = T * T3 (overwrites T2)
    {
        float p = (lane < 4) ? Bm[(4 * warp + lane) * 129] : 0.f;
        p = wred(p);
        if (lane == 0) part[32 + warp] = p;            // t3
        if (warp == 31 && lane == 0) {
            res[8]  = Bm[li * 129] + Bm[lj * 129];
            res[15] = Bm[li * 128 + lj] + Bm[lj * 128 + li];
        }
    }
    spstep(Bm, A, sv, sr, warp, lane);
    __syncthreads();                                              // (4)

    // phase C: t4, t5 partials; t6/t7/t8 walk; k4/k5 entries; column extraction
    {
        float p4 = (lane < 4) ? A[(4 * warp + lane) * 129] : 0.f;
        float p5 = 0.f;
        if (lane < 4) {
            int rw = 4 * warp + lane;
            #pragma unroll
            for (int k = 0; k < 9; ++k)
                p5 = fmaf(sv[rw * 10 + k], A[sr[rw * 10 + k] * 128 + rw], p5);
        }
        float t6 = 0.f, t7 = 0.f, t8 = 0.f;
        // strips d = 1..63: each unordered pair once, weight 2 (symmetry)
        for (int g = tid; g < 8064; g += CT) {
            int d = (g >> 7) + 1;
            int a = g & 127;
            int y = (a + d) & 127;
            float x3ab = Bm[a * 128 + y], x3ba = Bm[y * 128 + a];
            float x4ab = A[a * 128 + y],  x4ba = A[y * 128 + a];
            t6 = fmaf(2.f * x3ab, x3ba, t6);
            t7 = fmaf(x3ab, x4ba, fmaf(x3ba, x4ab, t7));
            t8 = fmaf(2.f * x4ab, x4ba, t8);
        }
        if (tid < 64) {    // d = 64 strip, each pair once over a<64
            int a = tid, y = a + 64;
            float x3ab = Bm[a * 128 + y], x3ba = Bm[y * 128 + a];
            float x4ab = A[a * 128 + y],  x4ba = A[y * 128 + a];
            t6 = fmaf(2.f * x3ab, x3ba, t6);
            t7 = fmaf(x3ab, x4ba, fmaf(x3ba, x4ab, t7));
            t8 = fmaf(2.f * x4ab, x4ba, t8);
        }
        if (tid < 128) {   // diagonal
            float d3 = Bm[tid * 129], d4 = A[tid * 129];
            t6 = fmaf(d3, d3, t6);
            t7 = fmaf(d3, d4, t7);
            t8 = fmaf(d4, d4, t8);
        }
        p4 = wred(p4); p5 = wred(p5);
        t6 = wred(t6); t7 = wred(t7); t8 = wred(t8);
        if (lane == 0) {
            part[2 * 32 + warp] = p4;
            part[3 * 32 + warp] = p5;
            part[4 * 32 + warp] = t6;
            part[5 * 32 + warp] = t7;
            part[6 * 32 + warp] = t8;
        }
        if (warp == 31 && lane == 0) {
            res[9]  = A[li * 129] + A[lj * 129];
            res[16] = A[li * 128 + lj] + A[lj * 128 + li];
        }
        if (warp == 30 && lane < 4) {   // k=5 entries: ii, ij, ji, jj
            int u = (lane < 2) ? li : lj;
            int v = (lane & 1) ? lj : li;
            float s = 0.f;
            #pragma unroll
            for (int k = 0; k < 9; ++k)
                s = fmaf(sv[u * 10 + k], A[sr[u * 10 + k] * 128 + v], s);
            ebuf[12 + lane] = s;
        }
        if (tid >= 512) {   // extract columns li/lj of T3 (Bm) and T4 (A)
            int t = tid - 512;
            int w = t >> 7, m = t & 127;
            const float* M = (w < 2) ? Bm : A;
            int v = (w & 1) ? lj : li;
            colb[w * 128 + m] = M[m * 128 + v];
        }
    }
    __syncthreads();                                              // (5)

    // phase D: 12 row.col dots (k=6,7,8 entries) + final trace reductions
    if (warp < 12) {
        const float* R; int u; const float* C;
        if (warp < 4)      { R = Bm; u = (warp < 2) ? li : lj; C = colb + (warp & 1) * 128; }
        else if (warp < 8) { R = Bm; u = (warp < 6) ? li : lj; C = colb + (2 + (warp & 1)) * 128; }
        else               { R = A;  u = (warp < 10) ? li : lj; C = colb + (2 + (warp & 1)) * 128; }
        float s = 0.f;
        #pragma unroll
        for (int q = 0; q < 4; ++q) { int m = lane + 32 * q; s = fmaf(R[u * 128 + m], C[m], s); }
        s = wred(s);
        if (lane == 0) ebuf[warp] = s;
    }
    if (warp >= 16 && warp < 23) {
        float s = part[(warp - 16) * 32 + lane];
        s = wred(s);
        if (lane == 0) res[warp - 16] = s;   // t2..t8 -> res[0..6]
    }
    __syncthreads();                                              // (6)
    if (tid == 0) {
        res[10] = ebuf[12] + ebuf[15];  res[17] = ebuf[13] + ebuf[14];  // nl5, ll5
        res[11] = ebuf[0] + ebuf[3];    res[18] = ebuf[1] + ebuf[2];    // nl6, ll6
        res[12] = ebuf[4] + ebuf[7];    res[19] = ebuf[5] + ebuf[6];    // nl7, ll7
        res[13] = ebuf[8] + ebuf[11];   res[20] = ebuf[9] + ebuf[10];   // nl8, ll8
    }
    __syncthreads();                                              // (7)
    if (tid < 21) g_feats[(size_t)bid * 21 + tid] = res[tid];
}

// ============================================================================
// Kernel 3: feature assembly + MLP
// ============================================================================
__global__ void mlp_kernel(const float* __restrict__ W1, const float* __restrict__ b1,
                           const float* __restrict__ W2, const float* __restrict__ b2,
                           float* __restrict__ out) {
    const int b = blockIdx.x;
    const int t = threadIdx.x;
    __shared__ float feat[72];

    for (int s = t; s < 72; s += 32) {
        float v;
        if (s < 14) {                       // gl = trace_p - trace_m
            int h = s / 7, k = s % 7;
            v = g_feats[((size_t)(h * 256 + b)) * 21 + k]
              - g_feats[((size_t)((2 + h) * 256 + b)) * 21 + k];
        } else if (s < 16) {                // omega
            v = g_omega[b * 2 + (s - 14)];
        } else {
            int m = (s - 16) % 14;
            int blk = (s - 16) / 14;        // 0 nlp, 1 nlm, 2 llp, 3 llm
            int h = m / 7, k = m % 7;
            int sgn = blk & 1;
            int off = (blk < 2) ? 7 : 14;
            v = g_feats[((size_t)((sgn * 2 + h) * 256 + b)) * 21 + off + k];
        }
        feat[s] = v;
    }
    __syncwarp();

    float h1 = b1[t];
    #pragma unroll 8
    for (int m = 0; m < 72; ++m) h1 = fmaf(feat[m], W1[m * 32 + t], h1);
    h1 = fmaxf(h1, 0.f);
    float v = h1 * W2[t];
    #pragma unroll
    for (int off = 16; off; off >>= 1) v += __shfl_down_sync(0xffffffffu, v, off);
    if (t == 0) out[b] = v + b2[0];
}

// ============================================================================
extern "C" void kernel_launch(void* const* d_in, const int* in_sizes, int n_in,
                              void* d_out, int out_size) {
    (void)in_sizes; (void)n_in; (void)out_size;
    const float* z_table = (const float*)d_in[0];
    const float* conv_W  = (const float*)d_in[1];
    const float* conv_b  = (const float*)d_in[2];
    const float* k1_W    = (const float*)d_in[3];
    const float* k1_b    = (const float*)d_in[4];
    const float* q1_W    = (const float*)d_in[5];
    const float* q1_b    = (const float*)d_in[6];
    const float* k2_W    = (const float*)d_in[7];
    const float* k2_b    = (const float*)d_in[8];
    const float* q2_W    = (const float*)d_in[9];
    const float* q2_b    = (const float*)d_in[10];
    const float* mlp_W1  = (const float*)d_in[11];
    const float* mlp_b1  = (const float*)d_in[12];
    const float* mlp_W2  = (const float*)d_in[13];
    const float* mlp_b2  = (const float*)d_in[14];
    const int*   z        = (const int*)d_in[15];
    const int*   edge_row = (const int*)d_in[16];
    const int*   node_i   = (const int*)d_in[20];
    const int*   node_j   = (const int*)d_in[21];
    float* out = (float*)d_out;

    cudaFuncSetAttribute(batch_kernel, cudaFuncAttributeMaxDynamicSharedMemorySize, SMB_FLOATS * 4);
    cudaFuncSetAttribute(chain_kernel, cudaFuncAttributeMaxDynamicSharedMemorySize, SMC_FLOATS * 4);

    batch_kernel<<<NB, 256, SMB_FLOATS * 4>>>(
        z_table, conv_W, conv_b, k1_W, k1_b, q1_W, q1_b,
        k2_W, k2_b, q2_W, q2_b, z, edge_row, node_i, node_j);
    chain_kernel<<<4 * NB, CT, SMC_FLOATS * 4>>>(node_i, node_j);
    mlp_kernel<<<NB, 32>>>(mlp_W1, mlp_b1, mlp_W2, mlp_b2, out);
}

// round 7
// speedup vs baseline: 5.2336x; 1.5432x over previous
#include <cuda_runtime.h>
#include <math.h>

#define NB 256

// Compact global scratch (static; no runtime allocation)
__device__ float g_vals[(size_t)2 * 256 * 128 * 12];  // [h][b][c]{ews0..7, ec, invp, invm, pad}
__device__ uint2 g_rows[256 * 128];                   // [b][c] 8 packed row bytes
__device__ float g_feats[4 * NB * 21];                // m-chains at slots (2+h)*256+b
__device__ float g_ent[2 * 256 * 36];                 // [h][b]: T^a entries (a=0..8)x{ii,ij,ji,jj}
__device__ float g_omega[NB * 2];

// ============================================================================
// Kernel 1: per-batch GCN + attention (unchanged from R6)
// ============================================================================
#define SMB_FLOATS 27524

__device__ __forceinline__ void copyW(const float* __restrict__ Wg, float* Wb,
                                      int n4, int tid) {
    const float4* s = (const float4*)Wg;
    float4* d = (float4*)Wb;
    for (int i = tid; i < n4; i += 256) d[i] = __ldg(s + i);
}

__device__ __forceinline__ void gemm32(const float* __restrict__ In,
                                       const float* __restrict__ Wb,
                                       const float* __restrict__ bias,
                                       float* __restrict__ Out, int tid, int act) {
    const int tr = (tid >> 3) * 4;
    const int tc = tid & 7;
    float acc[4][4];
    #pragma unroll
    for (int i = 0; i < 4; ++i)
        #pragma unroll
        for (int u = 0; u < 4; ++u) acc[i][u] = 0.f;
    #pragma unroll
    for (int m = 0; m < 32; ++m) {
        float a0 = In[(tr + 0) * 33 + m], a1 = In[(tr + 1) * 33 + m];
        float a2 = In[(tr + 2) * 33 + m], a3 = In[(tr + 3) * 33 + m];
        #pragma unroll
        for (int u = 0; u < 4; ++u) {
            float w = Wb[m * 32 + tc + 8 * u];
            acc[0][u] = fmaf(a0, w, acc[0][u]);
            acc[1][u] = fmaf(a1, w, acc[1][u]);
            acc[2][u] = fmaf(a2, w, acc[2][u]);
            acc[3][u] = fmaf(a3, w, acc[3][u]);
        }
    }
    #pragma unroll
    for (int i = 0; i < 4; ++i)
        #pragma unroll
        for (int u = 0; u < 4; ++u) {
            float s = acc[i][u];
            if (act) {
                s += __ldg(bias + tc + 8 * u);
                s = (s > 0.f) ? s : 0.2f * s;
            }
            Out[(tr + i) * 33 + tc + 8 * u] = s;
        }
}

__device__ __forceinline__ void gemm64(const float* __restrict__ In,
                                       const float* __restrict__ Wb,
                                       const float* __restrict__ bias,
                                       float* __restrict__ Out, int tid) {
    const int tr = (tid >> 3) * 4;
    const int tc = tid & 7;
    float acc[4][8];
    #pragma unroll
    for (int i = 0; i < 4; ++i)
        #pragma unroll
        for (int u = 0; u < 8; ++u) acc[i][u] = 0.f;
    #pragma unroll
    for (int m = 0; m < 32; ++m) {
        float a0 = In[(tr + 0) * 33 + m], a1 = In[(tr + 1) * 33 + m];
        float a2 = In[(tr + 2) * 33 + m], a3 = In[(tr + 3) * 33 + m];
        #pragma unroll
        for (int u = 0; u < 8; ++u) {
            float w = Wb[m * 64 + tc + 8 * u];
            acc[0][u] = fmaf(a0, w, acc[0][u]);
            acc[1][u] = fmaf(a1, w, acc[1][u]);
            acc[2][u] = fmaf(a2, w, acc[2][u]);
            acc[3][u] = fmaf(a3, w, acc[3][u]);
        }
    }
    #pragma unroll
    for (int i = 0; i < 4; ++i)
        #pragma unroll
        for (int u = 0; u < 8; ++u)
            Out[(tr + i) * 65 + tc + 8 * u] = acc[i][u] + __ldg(bias + tc + 8 * u);
}

__global__ __launch_bounds__(256, 2) void batch_kernel(
    const float* __restrict__ z_table, const float* __restrict__ conv_W, const float* __restrict__ conv_b,
    const float* __restrict__ k1_W, const float* __restrict__ k1_b,
    const float* __restrict__ q1_W, const float* __restrict__ q1_b,
    const float* __restrict__ k2_W, const float* __restrict__ k2_b,
    const float* __restrict__ q2_W, const float* __restrict__ q2_b,
    const int* __restrict__ z, const int* __restrict__ edge_row,
    const int* __restrict__ node_i, const int* __restrict__ node_j)
{
    extern __shared__ float sm[];
    float* Wb   = sm;            // 2048
    float* X    = sm + 2048;     // stride 33
    float* XW   = sm + 6272;     // stride 33
    float* Q2   = sm + 10496;    // stride 65
    float* K2   = sm + 18816;    // stride 65
    float* dinv = sm + 27136;
    float* wcs  = sm + 27264;
    unsigned char* rows8 = (unsigned char*)(sm + 27268);

    const int tid   = threadIdx.x;
    const int b     = blockIdx.x;
    const int gbase = b * 128;
    const int ebase = b * 1024;
    const int li    = node_i[b] - gbase;
    const int lj    = node_j[b] - gbase;

    if (tid < 128) {
        float dg = 9.f + (tid == li ? 1.f : 0.f) + (tid == lj ? 1.f : 0.f);
        dinv[tid] = rsqrtf(dg);
    }
    for (int e = tid; e < 1024; e += 256)
        rows8[(e & 127) * 8 + (e >> 7)] = (unsigned char)(edge_row[ebase + e] - gbase);
    for (int i = tid; i < 4096; i += 256) {
        int r = i >> 5, f = i & 31;
        X[r * 33 + f] = __ldg(z_table + __ldg(z + gbase + r) * 32 + f);
    }
    __syncthreads();

    const int warp = tid >> 5, lane = tid & 31;

    for (int l = 0; l < 3; ++l) {
        copyW(conv_W + l * 1024, Wb, 256, tid);
        __syncthreads();
        gemm32(X, Wb, nullptr, XW, tid, 0);
        __syncthreads();
        for (int it = 0; it < 16; ++it) {
            int c = it * 8 + warp;
            float dc = dinv[c];
            float acc = __ldg(conv_b + l * 32 + lane) + dc * dc * XW[c * 33 + lane];
            #pragma unroll
            for (int k = 0; k < 8; ++k) {
                int r = rows8[c * 8 + k];
                acc = fmaf(dinv[r] * dc, XW[r * 33 + lane], acc);
            }
            if (c == li)      acc = fmaf(dinv[lj] * dc, XW[lj * 33 + lane], acc);
            else if (c == lj) acc = fmaf(dinv[li] * dc, XW[li * 33 + lane], acc);
            X[c * 33 + lane] = (l < 2) ? fmaxf(acc, 0.f) : acc;
        }
        __syncthreads();
    }

    copyW(k1_W, Wb, 256, tid);  __syncthreads();
    gemm32(X, Wb, k1_b, XW, tid, 1);  __syncthreads();
    copyW(k2_W, Wb, 512, tid);  __syncthreads();
    gemm64(XW, Wb, k2_b, Q2, tid);  __syncthreads();
    copyW(q1_W, Wb, 256, tid);  __syncthreads();
    gemm32(X, Wb, q1_b, XW, tid, 1);  __syncthreads();
    copyW(q2_W, Wb, 512, tid);  __syncthreads();
    gemm64(XW, Wb, q2_b, K2, tid);  __syncthreads();

    const int c = tid & 127;
    const int h = tid >> 7;
    const float isq = 0.17677669529663687f;

    float kv[32];
    #pragma unroll
    for (int f = 0; f < 32; ++f) kv[f] = K2[c * 65 + h * 32 + f];

    float w[8];
    int rws[8];
    #pragma unroll
    for (int k = 0; k < 8; ++k) {
        int r = rows8[c * 8 + k];
        rws[k] = r;
        float s = 0.f;
        #pragma unroll 8
        for (int f = 0; f < 32; ++f) s = fmaf(Q2[r * 65 + h * 32 + f], kv[f], s);
        w[k] = s * isq;
    }
    bool cand = (c == li) || (c == lj);
    float w8 = 0.f;
    if (cand) {
        int r = (c == li) ? lj : li;
        float s = 0.f;
        #pragma unroll 8
        for (int f = 0; f < 32; ++f) s = fmaf(Q2[r * 65 + h * 32 + f], kv[f], s);
        w8 = s * isq;
        wcs[h * 2 + (c == li ? 1 : 0)] = 1.f / (1.f + expf(-w8));
    }
    float wmax = w[0];
    #pragma unroll
    for (int k = 1; k < 8; ++k) wmax = fmaxf(wmax, w[k]);
    if (cand) wmax = fmaxf(wmax, w8);

    float ews[8];
    float sum8 = 0.f;
    #pragma unroll
    for (int k = 0; k < 8; ++k) { ews[k] = expf(w[k] - wmax); sum8 += ews[k]; }
    float ec = cand ? expf(w8 - wmax) : 0.f;
    float invp = 1.f / (sum8 + ec + 1e-16f);
    float invm = 1.f / (sum8 + 1e-16f);

    size_t vb = (((size_t)h * 256 + b) * 128 + c) * 12;
    *(float4*)(g_vals + vb)     = make_float4(ews[0], ews[1], ews[2], ews[3]);
    *(float4*)(g_vals + vb + 4) = make_float4(ews[4], ews[5], ews[6], ews[7]);
    *(float4*)(g_vals + vb + 8) = make_float4(ec, invp, invm, 0.f);
    if (h == 0) {
        uint2 pk;
        pk.x = (unsigned)rws[0] | ((unsigned)rws[1] << 8) | ((unsigned)rws[2] << 16) | ((unsigned)rws[3] << 24);
        pk.y = (unsigned)rws[4] | ((unsigned)rws[5] << 8) | ((unsigned)rws[6] << 16) | ((unsigned)rws[7] << 24);
        g_rows[b * 128 + c] = pk;
    }
    __syncthreads();
    if (tid < 2) g_omega[b * 2 + tid] = wcs[tid * 2] + wcs[tid * 2 + 1];
}

// ============================================================================
// Kernel 2: per-(h,b) m-chain only (512 CTAs; T has exactly 8 nnz/row).
// Exports traces t2..8, nl/ll (m), and entries T^a[{i,j}^2] for a=0..8.
// ============================================================================
#define CT 1024
#define SMC_FLOATS 36128

__device__ __forceinline__ float wred(float v) {
    #pragma unroll
    for (int off = 16; off; off >>= 1) v += __shfl_down_sync(0xffffffffu, v, off);
    return v;
}

__device__ __forceinline__ void spstep(const float* __restrict__ In, float* __restrict__ Out,
                                       const float* __restrict__ sv, const int* __restrict__ sr,
                                       int warp, int lane) {
    const float4* In4 = (const float4*)In;
    #pragma unroll
    for (int it = 0; it < 4; ++it) {
        int c = it * 32 + warp;
        float v[8]; int r[8];
        #pragma unroll
        for (int k = 0; k < 8; ++k) { v[k] = sv[c * 10 + k]; r[k] = sr[c * 10 + k]; }
        float4 acc = make_float4(0.f, 0.f, 0.f, 0.f);
        #pragma unroll
        for (int k = 0; k < 8; ++k) {
            float4 x = In4[r[k] * 32 + lane];
            acc.x = fmaf(v[k], x.x, acc.x);
            acc.y = fmaf(v[k], x.y, acc.y);
            acc.z = fmaf(v[k], x.z, acc.z);
            acc.w = fmaf(v[k], x.w, acc.w);
        }
        *(float4*)(Out + c * 128 + lane * 4) = acc;
    }
}

__global__ __launch_bounds__(CT) void chain_kernel(const int* __restrict__ node_i,
                                                   const int* __restrict__ node_j) {
    extern __shared__ float sm[];
    float* A    = sm;            // T2, later T4
    float* Bm   = sm + 16384;    // T3
    float* sv   = sm + 32768;    // [128][10] (8 used)
    int*   sr   = (int*)(sm + 34048);
    float* colb = sm + 35328;    // 4 x 128
    float* part = sm + 35840;    // [7][32]
    float* res  = sm + 36064;    // 16 (t2..t8)
    float* ent  = sm + 36080;    // [9][4] {ii,ij,ji,jj}

    const int tid  = threadIdx.x;
    const int bid  = blockIdx.x;
    const int h    = bid >> 8;
    const int b    = bid & 255;
    const int li   = node_i[b] - b * 128;
    const int lj   = node_j[b] - b * 128;
    const int warp = tid >> 5, lane = tid & 31;

    if (tid < 128) {
        int c = tid;
        uint2 pr = g_rows[b * 128 + c];
        const float4* gv = (const float4*)(g_vals + (((size_t)h * 256 + b) * 128 + c) * 12);
        float4 v0 = gv[0], v1 = gv[1], v2 = gv[2];
        float inv = v2.z;   // invm
        float ev[8] = {v0.x, v0.y, v0.z, v0.w, v1.x, v1.y, v1.z, v1.w};
        #pragma unroll
        for (int k = 0; k < 4; ++k) {
            sr[c * 10 + k]     = (pr.x >> (8 * k)) & 255;
            sr[c * 10 + 4 + k] = (pr.y >> (8 * k)) & 255;
        }
        #pragma unroll
        for (int k = 0; k < 8; ++k) sv[c * 10 + k] = ev[k] * inv;
    }
    for (int i = tid; i < 4096; i += CT)
        *(float4*)(A + i * 4) = make_float4(0.f, 0.f, 0.f, 0.f);
    __syncthreads();                                              // (1)

    // T2 scatter (8x8)
    if (tid < 128) {
        int c = tid;
        #pragma unroll
        for (int k = 0; k < 8; ++k) {
            float v = sv[c * 10 + k];
            int r = sr[c * 10 + k];
            #pragma unroll
            for (int j = 0; j < 8; ++j)
                A[c * 128 + sr[r * 10 + j]] += v * sv[r * 10 + j];
        }
    }
    __syncthreads();                                              // (2)

    // phase A: t2 partials, ent[0..2]; then T3 = T*T2
    {
        float p = (lane < 4) ? A[(4 * warp + lane) * 129] : 0.f;
        p = wred(p);
        if (lane == 0) part[warp] = p;
        if (warp == 31 && lane == 0) {
            ent[8]  = A[li * 129];        ent[9]  = A[li * 128 + lj];
            ent[10] = A[lj * 128 + li];   ent[11] = A[lj * 129];
        }
        if (warp == 28 && lane == 0) { ent[0] = 1.f; ent[1] = 0.f; ent[2] = 0.f; ent[3] = 1.f; }
        if (warp == 29 && lane < 2) {   // ent a=1 from sparse rep
            int u = lane ? lj : li;
            float eu = 0.f, ev_ = 0.f;
            #pragma unroll
            for (int k = 0; k < 8; ++k) {
                int r = sr[u * 10 + k];
                float v = sv[u * 10 + k];
                if (r == li) eu += v;
                if (r == lj) ev_ += v;
            }
            ent[4 + 2 * lane] = eu;       // row u, col i
            ent[5 + 2 * lane] = ev_;      // row u, col j
        }
    }
    spstep(A, Bm, sv, sr, warp, lane);
    __syncthreads();                                              // (3)

    // phase B: t3 partials + ent[3]; then T4 = T*T3 (overwrites T2)
    {
        float p = (lane < 4) ? Bm[(4 * warp + lane) * 129] : 0.f;
        p = wred(p);
        if (lane == 0) part[32 + warp] = p;
        if (warp == 31 && lane == 0) {
            ent[12] = Bm[li * 129];       ent[13] = Bm[li * 128 + lj];
            ent[14] = Bm[lj * 128 + li];  ent[15] = Bm[lj * 129];
        }
    }
    spstep(Bm, A, sv, sr, warp, lane);
    __syncthreads();                                              // (4)

    // phase C: t4/t5 partials, walk, ent[4..5], columns
    {
        float p4 = (lane < 4) ? A[(4 * warp + lane) * 129] : 0.f;
        float p5 = 0.f;
        if (lane < 4) {
            int rw = 4 * warp + lane;
            #pragma unroll
            for (int k = 0; k < 8; ++k)
                p5 = fmaf(sv[rw * 10 + k], A[sr[rw * 10 + k] * 128 + rw], p5);
        }
        float t6 = 0.f, t7 = 0.f, t8 = 0.f;
        for (int g = tid; g < 8064; g += CT) {
            int d = (g >> 7) + 1;
            int a = g & 127;
            int y = (a + d) & 127;
            float x3ab = Bm[a * 128 + y], x3ba = Bm[y * 128 + a];
            float x4ab = A[a * 128 + y],  x4ba = A[y * 128 + a];
            t6 = fmaf(2.f * x3ab, x3ba, t6);
            t7 = fmaf(x3ab, x4ba, fmaf(x3ba, x4ab, t7));
            t8 = fmaf(2.f * x4ab, x4ba, t8);
        }
        if (tid < 64) {
            int a = tid, y = a + 64;
            float x3ab = Bm[a * 128 + y], x3ba = Bm[y * 128 + a];
            float x4ab = A[a * 128 + y],  x4ba = A[y * 128 + a];
            t6 = fmaf(2.f * x3ab, x3ba, t6);
            t7 = fmaf(x3ab, x4ba, fmaf(x3ba, x4ab, t7));
            t8 = fmaf(2.f * x4ab, x4ba, t8);
        }
        if (tid < 128) {
            float d3 = Bm[tid * 129], d4 = A[tid * 129];
            t6 = fmaf(d3, d3, t6);
            t7 = fmaf(d3, d4, t7);
            t8 = fmaf(d4, d4, t8);
        }
        p4 = wred(p4); p5 = wred(p5);
        t6 = wred(t6); t7 = wred(t7); t8 = wred(t8);
        if (lane == 0) {
            part[2 * 32 + warp] = p4;
            part[3 * 32 + warp] = p5;
            part[4 * 32 + warp] = t6;
            part[5 * 32 + warp] = t7;
            part[6 * 32 + warp] = t8;
        }
        if (warp == 31 && lane == 0) {
            ent[16] = A[li * 129];        ent[17] = A[li * 128 + lj];
            ent[18] = A[lj * 128 + li];   ent[19] = A[lj * 129];
        }
        if (warp == 30 && lane < 4) {   // ent a=5 (ii,ij,ji,jj)
            int u = (lane < 2) ? li : lj;
            int v = (lane & 1) ? lj : li;
            float s = 0.f;
            #pragma unroll
            for (int k = 0; k < 8; ++k)
                s = fmaf(sv[u * 10 + k], A[sr[u * 10 + k] * 128 + v], s);
            ent[20 + lane] = s;
        }
        if (tid >= 512) {
            int t = tid - 512;
            int w = t >> 7, m = t & 127;
            const float* M = (w < 2) ? Bm : A;
            int v = (w & 1) ? lj : li;
            colb[w * 128 + m] = M[m * 128 + v];
        }
    }
    __syncthreads();                                              // (5)

    // phase D: 12 dots -> ent[6..8]; final trace reductions -> res[0..6]
    if (warp < 12) {
        const float* R; int u; const float* C;
        if (warp < 4)      { R = Bm; u = (warp < 2) ? li : lj; C = colb + (warp & 1) * 128; }
        else if (warp < 8) { R = Bm; u = (warp < 6) ? li : lj; C = colb + (2 + (warp & 1)) * 128; }
        else               { R = A;  u = (warp < 10) ? li : lj; C = colb + (2 + (warp & 1)) * 128; }
        float s = 0.f;
        #pragma unroll
        for (int q = 0; q < 4; ++q) { int m = lane + 32 * q; s = fmaf(R[u * 128 + m], C[m], s); }
        s = wred(s);
        if (lane == 0) ent[(6 + (warp >> 2)) * 4 + (warp & 3)] = s;
    }
    if (warp >= 16 && warp < 23) {
        float s = part[(warp - 16) * 32 + lane];
        s = wred(s);
        if (lane == 0) res[warp - 16] = s;
    }
    __syncthreads();                                              // (6)

    const size_t mc = (size_t)(2 + h) * 256 + b;
    if (tid < 7)       g_feats[mc * 21 + tid] = res[tid];
    else if (tid < 14) { int k = tid - 7 + 2;  g_feats[mc * 21 + tid] = ent[k * 4] + ent[k * 4 + 3]; }
    else if (tid < 21) { int k = tid - 14 + 2; g_feats[mc * 21 + tid] = ent[k * 4 + 1] + ent[k * 4 + 2]; }
    else if (tid < 57) g_ent[((size_t)h * 256 + b) * 36 + tid - 21] = ent[tid - 21];
}

// ============================================================================
// Kernel 3: rank-2 correction DP (p-chain features) + feature assembly + MLP
// ============================================================================
__device__ __forceinline__ void mul22(float* d, const float* a, const float* b) {
    d[0] = a[0] * b[0] + a[1] * b[2];
    d[1] = a[0] * b[1] + a[1] * b[3];
    d[2] = a[2] * b[0] + a[3] * b[2];
    d[3] = a[2] * b[1] + a[3] * b[3];
}

__global__ void mlp_kernel(const float* __restrict__ W1, const float* __restrict__ b1,
                           const float* __restrict__ W2, const float* __restrict__ b2,
                           const int* __restrict__ node_i, const int* __restrict__ node_j,
                           float* __restrict__ out) {
    const int b = blockIdx.x;
    const int t = threadIdx.x;
    __shared__ float feat[72];
    __shared__ float mf[2][21];
    __shared__ float ent[2][36];
    __shared__ float pf[2][21];
    __shared__ float scr[2][144];   // per h: G 32 | Wp 32 | Wn 32 | Xc 36 | tc 9

    for (int q = t; q < 42; q += 32) mf[q / 21][q % 21] = g_feats[((size_t)(2 + q / 21) * 256 + b) * 21 + q % 21];
    for (int q = t; q < 72; q += 32) ent[q / 36][q % 36] = g_ent[((size_t)(q / 36) * 256 + b) * 36 + q % 36];
    __syncwarp();

    if (t == 0 || t == 16) {
        const int h = t >> 4;
        const float* E = ent[h];
        float* G  = scr[h];
        float* Wp = scr[h] + 32;
        float* Wn = scr[h] + 64;
        float* Xc = scr[h] + 96;   // [9][4]
        float* tc = scr[h] + 132;  // [9]
        const int li = node_i[b] - b * 128;
        const int lj = node_j[b] - b * 128;
        const float* gvi = g_vals + (((size_t)h * 256 + b) * 128 + li) * 12 + 8;
        const float* gvj = g_vals + (((size_t)h * 256 + b) * 128 + lj) * 12 + 8;
        float ai = gvi[1] / gvi[2], bi = gvi[0] * gvi[1];
        float aj = gvj[1] / gvj[2], bj = gvj[0] * gvj[1];

        #pragma unroll 1
        for (int a = 0; a < 8; ++a) {
            G[a * 4 + 0] = (ai - 1.f) * E[(a + 1) * 4 + 0] + bi * E[a * 4 + 2];
            G[a * 4 + 1] = (ai - 1.f) * E[(a + 1) * 4 + 1] + bi * E[a * 4 + 3];
            G[a * 4 + 2] = (aj - 1.f) * E[(a + 1) * 4 + 2] + bj * E[a * 4 + 0];
            G[a * 4 + 3] = (aj - 1.f) * E[(a + 1) * 4 + 3] + bj * E[a * 4 + 1];
        }
        #pragma unroll 1
        for (int k = 0; k < 9; ++k) { tc[k] = 0.f; Xc[k * 4] = 0.f; Xc[k * 4 + 1] = 0.f; Xc[k * 4 + 2] = 0.f; Xc[k * 4 + 3] = 0.f; }
        // c = 0: Wp[a] = G[a]
        #pragma unroll 1
        for (int a = 0; a < 8; ++a) {
            Wp[a * 4 + 0] = G[a * 4 + 0]; Wp[a * 4 + 1] = G[a * 4 + 1];
            Wp[a * 4 + 2] = G[a * 4 + 2]; Wp[a * 4 + 3] = G[a * 4 + 3];
            tc[a + 1] += G[a * 4 + 0] + G[a * 4 + 3];
        }
        #pragma unroll 1
        for (int bb = 0; bb < 8; ++bb) {   // Xc[b+1] += H_b * W_{0,0}
            float tmp[4];
            mul22(tmp, E + bb * 4, G);
            Xc[(bb + 1) * 4 + 0] += tmp[0]; Xc[(bb + 1) * 4 + 1] += tmp[1];
            Xc[(bb + 1) * 4 + 2] += tmp[2]; Xc[(bb + 1) * 4 + 3] += tmp[3];
        }
        #pragma unroll 1
        for (int c = 1; c < 8; ++c) {
            #pragma unroll 1
            for (int a = 0; a <= 7 - c; ++a) {
                float tmp[4];
                mul22(tmp, Wp, G + a * 4);   // W_{0,c-1} * G_a
                Wn[a * 4 + 0] = Wp[(a + 1) * 4 + 0] + tmp[0];
                Wn[a * 4 + 1] = Wp[(a + 1) * 4 + 1] + tmp[1];
                Wn[a * 4 + 2] = Wp[(a + 1) * 4 + 2] + tmp[2];
                Wn[a * 4 + 3] = Wp[(a + 1) * 4 + 3] + tmp[3];
                tc[a + c + 1] += Wn[a * 4 + 0] + Wn[a * 4 + 3];
            }
            #pragma unroll 1
            for (int bb = 0; bb <= 7 - c; ++bb) {   // Xc[b+c+1] += H_b * W_{0,c}
                float tmp[4];
                mul22(tmp, E + bb * 4, Wn);
                Xc[(bb + c + 1) * 4 + 0] += tmp[0]; Xc[(bb + c + 1) * 4 + 1] += tmp[1];
                Xc[(bb + c + 1) * 4 + 2] += tmp[2]; Xc[(bb + c + 1) * 4 + 3] += tmp[3];
            }
            #pragma unroll 1
            for (int a = 0; a <= 7 - c; ++a) {
                Wp[a * 4 + 0] = Wn[a * 4 + 0]; Wp[a * 4 + 1] = Wn[a * 4 + 1];
                Wp[a * 4 + 2] = Wn[a * 4 + 2]; Wp[a * 4 + 3] = Wn[a * 4 + 3];
            }
        }
        #pragma unroll 1
        for (int k = 2; k <= 8; ++k) {
            pf[h][k - 2]      = mf[h][k - 2] + tc[k];
            pf[h][7 + k - 2]  = E[k * 4 + 0] + E[k * 4 + 3] + Xc[k * 4 + 0] + Xc[k * 4 + 3];
            pf[h][14 + k - 2] = E[k * 4 + 1] + E[k * 4 + 2] + Xc[k * 4 + 1] + Xc[k * 4 + 2];
        }
    }
    __syncwarp();

    for (int s = t; s < 72; s += 32) {
        float v;
        if (s < 14) {
            int h = s / 7, k = s % 7;
            v = pf[h][k] - mf[h][k];
        } else if (s < 16) {
            v = g_omega[b * 2 + (s - 14)];
        } else {
            int m = (s - 16) % 14;
            int blk = (s - 16) / 14;
            int h = m / 7, k = m % 7;
            if (blk == 0)      v = pf[h][7 + k];
            else if (blk == 1) v = mf[h][7 + k];
            else if (blk == 2) v = pf[h][14 + k];
            else               v = mf[h][14 + k];
        }
        feat[s] = v;
    }
    __syncwarp();

    float h1 = b1[t];
    #pragma unroll 8
    for (int m = 0; m < 72; ++m) h1 = fmaf(feat[m], W1[m * 32 + t], h1);
    h1 = fmaxf(h1, 0.f);
    float v = h1 * W2[t];
    #pragma unroll
    for (int off = 16; off; off >>= 1) v += __shfl_down_sync(0xffffffffu, v, off);
    if (t == 0) out[b] = v + b2[0];
}

// ============================================================================
extern "C" void kernel_launch(void* const* d_in, const int* in_sizes, int n_in,
                              void* d_out, int out_size) {
    (void)in_sizes; (void)n_in; (void)out_size;
    const float* z_table = (const float*)d_in[0];
    const float* conv_W  = (const float*)d_in[1];
    const float* conv_b  = (const float*)d_in[2];
    const float* k1_W    = (const float*)d_in[3];
    const float* k1_b    = (const float*)d_in[4];
    const float* q1_W    = (const float*)d_in[5];
    const float* q1_b    = (const float*)d_in[6];
    const float* k2_W    = (const float*)d_in[7];
    const float* k2_b    = (const float*)d_in[8];
    const float* q2_W    = (const float*)d_in[9];
    const float* q2_b    = (const float*)d_in[10];
    const float* mlp_W1  = (const float*)d_in[11];
    const float* mlp_b1  = (const float*)d_in[12];
    const float* mlp_W2  = (const float*)d_in[13];
    const float* mlp_b2  = (const float*)d_in[14];
    const int*   z        = (const int*)d_in[15];
    const int*   edge_row = (const int*)d_in[16];
    const int*   node_i   = (const int*)d_in[20];
    const int*   node_j   = (const int*)d_in[21];
    float* out = (float*)d_out;

    cudaFuncSetAttribute(batch_kernel, cudaFuncAttributeMaxDynamicSharedMemorySize, SMB_FLOATS * 4);
    cudaFuncSetAttribute(chain_kernel, cudaFuncAttributeMaxDynamicSharedMemorySize, SMC_FLOATS * 4);

    batch_kernel<<<NB, 256, SMB_FLOATS * 4>>>(
        z_table, conv_W, conv_b, k1_W, k1_b, q1_W, q1_b,
        k2_W, k2_b, q2_W, q2_b, z, edge_row, node_i, node_j);
    chain_kernel<<<2 * NB, CT, SMC_FLOATS * 4>>>(node_i, node_j);
    mlp_kernel<<<NB, 32>>>(mlp_W1, mlp_b1, mlp_W2, mlp_b2, node_i, node_j, out);
}